// round 9
// baseline (speedup 1.0000x reference)
#include <cuda_runtime.h>
#include <cuda_bf16.h>
#include <math.h>
#include <stdint.h>

// Problem constants (fixed shapes)
constexpr int Bsz  = 2;
constexpr int Sseq = 2048;
constexpr int Fdim = 1024;
constexpr int Hh   = 16;
constexpr int Dh   = 64;
constexpr int Mrows = Bsz * Sseq;   // 4096

// Scratch (device globals, allocation-free). All operands live as TWO bf16
// planes: hi = bf16(x), mid = bf16(x - hi). hi+mid recovers fp32 to ~2^-16.
__device__ __nv_bfloat16 g_Afh[(size_t)Mrows * Fdim];  // attend_from planes
__device__ __nv_bfloat16 g_Afm[(size_t)Mrows * Fdim];
__device__ __nv_bfloat16 g_Ath[(size_t)Mrows * Fdim];  // attend_to planes
__device__ __nv_bfloat16 g_Atm[(size_t)Mrows * Fdim];
__device__ __nv_bfloat16 g_Wqh[(size_t)Fdim * Fdim];   // w_q^T  [n][k]
__device__ __nv_bfloat16 g_Wqm[(size_t)Fdim * Fdim];
__device__ __nv_bfloat16 g_Wkvh[(size_t)2 * Fdim * Fdim]; // w_kv^T [n][k]
__device__ __nv_bfloat16 g_Wkvm[(size_t)2 * Fdim * Fdim];
__device__ __nv_bfloat16 g_Woh[(size_t)Fdim * Fdim];   // w_out^T [n][k]
__device__ __nv_bfloat16 g_Wom[(size_t)Fdim * Fdim];
__device__ __nv_bfloat16 g_Qh[(size_t)Mrows * Fdim];   // Q planes [row][d]
__device__ __nv_bfloat16 g_Qm[(size_t)Mrows * Fdim];
__device__ __nv_bfloat16 g_Kh[(size_t)Mrows * Fdim];   // K planes [row][d]
__device__ __nv_bfloat16 g_Km[(size_t)Mrows * Fdim];
__device__ __nv_bfloat16 g_Vth[(size_t)Mrows * Fdim];  // V^T planes [b][h][d][s]
__device__ __nv_bfloat16 g_Vtm[(size_t)Mrows * Fdim];
__device__ __nv_bfloat16 g_Oh[(size_t)Mrows * Fdim];   // O planes [row][feat]
__device__ __nv_bfloat16 g_Om[(size_t)Mrows * Fdim];

// ---------------------------------------------------------------------------
// PTX helpers
// ---------------------------------------------------------------------------
__device__ __forceinline__ void cp_async16(uint32_t saddr, const void* gptr) {
    asm volatile("cp.async.cg.shared.global [%0], [%1], 16;"
                 :: "r"(saddr), "l"(gptr));
}
__device__ __forceinline__ void cp_commit() {
    asm volatile("cp.async.commit_group;");
}
__device__ __forceinline__ void cp_wait0() {
    asm volatile("cp.async.wait_group 0;");
}

__device__ __forceinline__ void mma_bf16(
    float& d0, float& d1, float& d2, float& d3,
    uint32_t a0, uint32_t a1, uint32_t a2, uint32_t a3,
    uint32_t b0, uint32_t b1)
{
    asm volatile(
        "mma.sync.aligned.m16n8k16.row.col.f32.bf16.bf16.f32 "
        "{%0,%1,%2,%3},{%4,%5,%6,%7},{%8,%9},{%0,%1,%2,%3};"
        : "+f"(d0), "+f"(d1), "+f"(d2), "+f"(d3)
        : "r"(a0), "r"(a1), "r"(a2), "r"(a3), "r"(b0), "r"(b1));
}

// ldmatrix x4: four 8x8 b16 matrices; lane l supplies row address.
__device__ __forceinline__ void ldsm_x4(
    uint32_t& r0, uint32_t& r1, uint32_t& r2, uint32_t& r3, uint32_t addr)
{
    asm volatile("ldmatrix.sync.aligned.m8n8.x4.shared.b16 {%0,%1,%2,%3}, [%4];"
                 : "=r"(r0), "=r"(r1), "=r"(r2), "=r"(r3) : "r"(addr));
}

__device__ __forceinline__ void bsplit(float v, __nv_bfloat16& h, __nv_bfloat16& m) {
    h = __float2bfloat16_rn(v);
    m = __float2bfloat16_rn(v - __bfloat162float(h));
}
__device__ __forceinline__ uint32_t bpack(__nv_bfloat16 lo, __nv_bfloat16 hi) {
    __nv_bfloat162 t;
    t.x = lo; t.y = hi;            // .x = low half = lower k index
    return *reinterpret_cast<uint32_t*>(&t);
}

// ---------------------------------------------------------------------------
// Pre-pass: elementwise split (no transpose) for activations [M][K].
// ---------------------------------------------------------------------------
__global__ __launch_bounds__(256) void asplit_kernel(
    const float* __restrict__ src, __nv_bfloat16* __restrict__ hi,
    __nv_bfloat16* __restrict__ mid, int n4)
{
    const int i = blockIdx.x * 256 + threadIdx.x;
    if (i >= n4) return;
    float4 v = ((const float4*)src)[i];
    __nv_bfloat16 h0, h1, h2, h3, m0, m1, m2, m3;
    bsplit(v.x, h0, m0); bsplit(v.y, h1, m1);
    bsplit(v.z, h2, m2); bsplit(v.w, h3, m3);
    uint2 hw = make_uint2(bpack(h0, h1), bpack(h2, h3));
    uint2 mw = make_uint2(bpack(m0, m1), bpack(m2, m3));
    ((uint2*)hi)[i] = hw;
    ((uint2*)mid)[i] = mw;
}

// Pre-pass: split + transpose weights w[k][n] -> planes [n][k].
__global__ __launch_bounds__(256) void wsplit_kernel(
    const float* __restrict__ w, __nv_bfloat16* __restrict__ th,
    __nv_bfloat16* __restrict__ tm, int K, int N)
{
    __shared__ float ts[32][33];
    const int k0 = blockIdx.x * 32;
    const int n0 = blockIdx.y * 32;
    const int tx = threadIdx.x & 31;
    const int ty = threadIdx.x >> 5;     // 0..7
    #pragma unroll
    for (int i = 0; i < 4; i++)
        ts[ty + 8 * i][tx] = w[(size_t)(k0 + ty + 8 * i) * N + n0 + tx];
    __syncthreads();
    #pragma unroll
    for (int i = 0; i < 4; i++) {
        float v = ts[tx][ty + 8 * i];
        __nv_bfloat16 h, m;
        bsplit(v, h, m);
        const size_t o = (size_t)(n0 + ty + 8 * i) * K + k0 + tx;
        th[o] = h;
        tm[o] = m;
    }
}

// ---------------------------------------------------------------------------
// bf16x3 GEMM core: C[M,N] = A[M,1024] @ W^T[n][k] (+bias via epilogue).
// 128x128 block tile, BK=32, 256 threads, 8 warps of 64x32 warp tiles.
// Hot loop: ldmatrix.x4 + HMMA only (3 MMAs per pair: am*bh, ah*bm, ah*bh).
// smem planes (uint32 words, bf16x2 packed along K): Ah|Am|Bh|Bm per stage.
// SW=20 word row stride -> ldmatrix 8-row groups hit disjoint bank quads.
// ---------------------------------------------------------------------------
constexpr int SW  = 20;                    // words per row (16 data + 4 pad)
constexpr int PLW = 128 * SW;              // 2560 words per plane
constexpr int STAGE_W = 4 * PLW;           // 10240 words per stage
constexpr int GEMM_SMEM = 2 * STAGE_W * 4; // 81920 B

template <typename EPI>
__device__ __forceinline__ void gemm_mainloop(
    const __nv_bfloat16* __restrict__ Ah, const __nv_bfloat16* __restrict__ Am,
    const __nv_bfloat16* __restrict__ Bh, const __nv_bfloat16* __restrict__ Bm,
    int m0, int n0, uint32_t* smw, EPI epi)
{
    const uint32_t sbase = (uint32_t)__cvta_generic_to_shared(smw);
    const int tid  = threadIdx.x;
    const int warp = tid >> 5;
    const int lane = tid & 31;
    const int rbase = (warp & 1) * 64;
    const int cbase = (warp >> 1) * 32;
    const int lq  = lane >> 2;      // 0..7
    const int lc  = lane & 3;       // 0..3
    // ldmatrix lane -> row/chunk mapping (same for A x4 and B-pair x4)
    const int lrow = (lane & 7) + ((lane >> 3) & 1) * 8;
    const int lcol = ((lane >> 4) & 1) * 4;

    float acc[4][4][4];
    #pragma unroll
    for (int i = 0; i < 4; i++)
        #pragma unroll
        for (int j = 0; j < 4; j++)
            #pragma unroll
            for (int r = 0; r < 4; r++) acc[i][j][r] = 0.f;

    auto load_tile = [&](int kt, int st) {
        const int k0 = kt * 32;
        const uint32_t base = sbase + (uint32_t)(st * STAGE_W) * 4u;
        #pragma unroll
        for (int it = 0; it < 2; it++) {
            const int slot = it * 256 + tid;
            const int row = slot >> 2, c4 = slot & 3;
            const uint32_t so = (uint32_t)(row * SW + c4 * 4) * 4u;
            const size_t ga = (size_t)(m0 + row) * 1024 + k0 + c4 * 8;
            const size_t gb = (size_t)(n0 + row) * 1024 + k0 + c4 * 8;
            cp_async16(base + so, &Ah[ga]);
            cp_async16(base + (uint32_t)(PLW * 4) + so, &Am[ga]);
            cp_async16(base + (uint32_t)(2 * PLW * 4) + so, &Bh[gb]);
            cp_async16(base + (uint32_t)(3 * PLW * 4) + so, &Bm[gb]);
        }
    };

    load_tile(0, 0);
    cp_commit();

    for (int kt = 0; kt < 32; kt++) {
        cp_wait0();
        __syncthreads();
        if (kt + 1 < 32) { load_tile(kt + 1, (kt + 1) & 1); cp_commit(); }

        const uint32_t stb = sbase + (uint32_t)((kt & 1) * STAGE_W) * 4u;

        #pragma unroll
        for (int ks = 0; ks < 2; ks++) {
            const int kk2 = ks * 8;
            uint32_t ah[4][4], am[4][4], bh[4][2], bm[4][2];
            #pragma unroll
            for (int mi = 0; mi < 4; mi++) {
                const uint32_t ad = stb +
                    (uint32_t)((rbase + mi * 16 + lrow) * SW + kk2 + lcol) * 4u;
                ldsm_x4(ah[mi][0], ah[mi][1], ah[mi][2], ah[mi][3], ad);
                ldsm_x4(am[mi][0], am[mi][1], am[mi][2], am[mi][3],
                        ad + (uint32_t)(PLW * 4));
            }
            #pragma unroll
            for (int njp = 0; njp < 2; njp++) {
                const uint32_t bd = stb + (uint32_t)(2 * PLW * 4) +
                    (uint32_t)((cbase + njp * 16 + lrow) * SW + kk2 + lcol) * 4u;
                uint32_t r0, r1, r2, r3;
                ldsm_x4(r0, r1, r2, r3, bd);
                bh[2 * njp][0] = r0; bh[2 * njp + 1][0] = r1;
                bh[2 * njp][1] = r2; bh[2 * njp + 1][1] = r3;
                ldsm_x4(r0, r1, r2, r3, bd + (uint32_t)(PLW * 4));
                bm[2 * njp][0] = r0; bm[2 * njp + 1][0] = r1;
                bm[2 * njp][1] = r2; bm[2 * njp + 1][1] = r3;
            }
            #pragma unroll
            for (int mi = 0; mi < 4; mi++)
                #pragma unroll
                for (int nj = 0; nj < 4; nj++) {
                    mma_bf16(acc[mi][nj][0], acc[mi][nj][1],
                             acc[mi][nj][2], acc[mi][nj][3],
                             am[mi][0], am[mi][1], am[mi][2], am[mi][3],
                             bh[nj][0], bh[nj][1]);
                    mma_bf16(acc[mi][nj][0], acc[mi][nj][1],
                             acc[mi][nj][2], acc[mi][nj][3],
                             ah[mi][0], ah[mi][1], ah[mi][2], ah[mi][3],
                             bm[nj][0], bm[nj][1]);
                    mma_bf16(acc[mi][nj][0], acc[mi][nj][1],
                             acc[mi][nj][2], acc[mi][nj][3],
                             ah[mi][0], ah[mi][1], ah[mi][2], ah[mi][3],
                             bh[nj][0], bh[nj][1]);
                }
        }
        __syncthreads();
    }

    epi(acc, rbase, cbase, lq, lc);
}

// Merged Q + KV projection. grid.x = 768.
//  bx <  256: Q tile -> (g_Qh, g_Qm)
//  bx >= 256: KV tile -> K planes or V^T planes
__global__ __launch_bounds__(256, 2) void qkv_gemm_kernel(
    const __nv_bfloat16* __restrict__ Afh, const __nv_bfloat16* __restrict__ Afm,
    const __nv_bfloat16* __restrict__ Ath, const __nv_bfloat16* __restrict__ Atm,
    const __nv_bfloat16* __restrict__ Wqh, const __nv_bfloat16* __restrict__ Wqm,
    const __nv_bfloat16* __restrict__ Wkvh, const __nv_bfloat16* __restrict__ Wkvm,
    const float* __restrict__ bq, const float* __restrict__ bkv,
    __nv_bfloat16* __restrict__ Qh, __nv_bfloat16* __restrict__ Qm,
    __nv_bfloat16* __restrict__ Kh, __nv_bfloat16* __restrict__ Km,
    __nv_bfloat16* __restrict__ Vth, __nv_bfloat16* __restrict__ Vtm)
{
    extern __shared__ uint32_t smw[];
    const int bx = blockIdx.x;

    const __nv_bfloat16 *Ah, *Am, *Bh, *Bm;
    const float* bias;
    int m0, n0, is_v = 0, ncol;
    if (bx < 256) {
        Ah = Afh; Am = Afm; Bh = Wqh; Bm = Wqm; bias = bq;
        m0 = (bx >> 3) * 128; n0 = (bx & 7) * 128; ncol = n0;
    } else {
        const int bxx = bx - 256;
        Ah = Ath; Am = Atm; Bh = Wkvh; Bm = Wkvm; bias = bkv;
        m0 = (bxx >> 4) * 128; n0 = (bxx & 15) * 128;
        if (n0 < 1024) { ncol = n0; }
        else           { ncol = n0 - 1024; is_v = 1; }
    }

    gemm_mainloop(Ah, Am, Bh, Bm, m0, n0, smw,
        [&](float (&acc)[4][4][4], int rbase, int cbase, int lq, int lc) {
            #pragma unroll
            for (int mi = 0; mi < 4; mi++) {
                const int r0 = m0 + rbase + mi * 16 + lq;
                #pragma unroll
                for (int nj = 0; nj < 4; nj++) {
                    const int col = ncol + cbase + nj * 8 + lc * 2;
                    const float b0 = bias[n0 - ncol + col];
                    const float b1 = bias[n0 - ncol + col + 1];
                    float v00 = acc[mi][nj][0] + b0;
                    float v01 = acc[mi][nj][1] + b1;
                    float v10 = acc[mi][nj][2] + b0;
                    float v11 = acc[mi][nj][3] + b1;
                    __nv_bfloat16 h00, h01, h10, h11, q00, q01, q10, q11;
                    bsplit(v00, h00, q00); bsplit(v01, h01, q01);
                    bsplit(v10, h10, q10); bsplit(v11, h11, q11);
                    if (!is_v) {
                        __nv_bfloat16* Dh = (bx < 256) ? Qh : Kh;
                        __nv_bfloat16* Dm = (bx < 256) ? Qm : Km;
                        const size_t o0 = (size_t)r0 * 1024 + col;
                        const size_t o1 = (size_t)(r0 + 8) * 1024 + col;
                        *(uint32_t*)&Dh[o0] = bpack(h00, h01);
                        *(uint32_t*)&Dh[o1] = bpack(h10, h11);
                        *(uint32_t*)&Dm[o0] = bpack(q00, q01);
                        *(uint32_t*)&Dm[o1] = bpack(q10, q11);
                    } else {
                        // V transposed: [b][h][d][s]
                        const int h = col >> 6, d = col & 63;
                        const int bl0 = r0 >> 11, s0 = r0 & 2047;
                        const int bl1 = (r0 + 8) >> 11, s1 = (r0 + 8) & 2047;
                        const size_t i00 = ((size_t)(bl0 * 16 + h) * 64 + d) * 2048 + s0;
                        const size_t i10 = ((size_t)(bl1 * 16 + h) * 64 + d) * 2048 + s1;
                        Vth[i00] = h00;          Vtm[i00] = q00;
                        Vth[i00 + 2048] = h01;   Vtm[i00 + 2048] = q01;
                        Vth[i10] = h10;          Vtm[i10] = q10;
                        Vth[i10 + 2048] = h11;   Vtm[i10 + 2048] = q11;
                    }
                }
            }
        });
}

// Output projection: out = O @ w_out + b_out (fp32 store).
__global__ __launch_bounds__(256, 2) void out_gemm_kernel(
    const __nv_bfloat16* __restrict__ Ah, const __nv_bfloat16* __restrict__ Am,
    const __nv_bfloat16* __restrict__ Bh, const __nv_bfloat16* __restrict__ Bm,
    const float* __restrict__ bias, float* __restrict__ C)
{
    extern __shared__ uint32_t smw[];
    const int m0 = blockIdx.y * 128;
    const int n0 = blockIdx.x * 128;
    gemm_mainloop(Ah, Am, Bh, Bm, m0, n0, smw,
        [&](float (&acc)[4][4][4], int rbase, int cbase, int lq, int lc) {
            #pragma unroll
            for (int mi = 0; mi < 4; mi++) {
                const int r0 = m0 + rbase + mi * 16 + lq;
                #pragma unroll
                for (int nj = 0; nj < 4; nj++) {
                    const int col = n0 + cbase + nj * 8 + lc * 2;
                    const float b0 = bias[col], b1 = bias[col + 1];
                    *(float2*)&C[(size_t)r0 * Fdim + col] =
                        make_float2(acc[mi][nj][0] + b0, acc[mi][nj][1] + b1);
                    *(float2*)&C[(size_t)(r0 + 8) * Fdim + col] =
                        make_float2(acc[mi][nj][2] + b0, acc[mi][nj][3] + b1);
                }
            }
        });
}

// ---------------------------------------------------------------------------
// bf16x3 flash attention. Br=128, Bc=64, d=64. 8 warps, 16 q-rows each.
// Q frags via direct LDG (once). K tiles [key][d], V^T tiles [d][key] via
// cp.async double-buffered; all smem fragment loads via ldmatrix.x4
// (FST=36 word stride -> conflict-free). S: 3 MMAs/pair; O: 3 MMAs/pair
// with P frags built directly from S-accumulator registers.
// Mask: z >= s -> -1e12f. CTA t does 2t+2 kv tiles (t=0: all 32).
// ---------------------------------------------------------------------------
constexpr int FST   = 36;                 // tile row stride in words
constexpr int FTW   = 64 * FST;           // 2304 words per plane-stage
constexpr int FLASH_SMEM = 8 * FTW * 4;   // 4 planes x 2 stages = 73728 B

__global__ __launch_bounds__(256) void flash_mma_kernel(
    const __nv_bfloat16* __restrict__ Qh, const __nv_bfloat16* __restrict__ Qm,
    const __nv_bfloat16* __restrict__ Kh, const __nv_bfloat16* __restrict__ Km,
    const __nv_bfloat16* __restrict__ Vth, const __nv_bfloat16* __restrict__ Vtm,
    __nv_bfloat16* __restrict__ Oh, __nv_bfloat16* __restrict__ Om)
{
    extern __shared__ uint32_t smw[];
    const uint32_t sbase = (uint32_t)__cvta_generic_to_shared(smw);

    const int x = blockIdx.x;
    const int t = (x == 0) ? 0 : (16 - x);     // heavy CTAs first
    const int h = blockIdx.y;
    const int b = blockIdx.z;
    const int tid  = threadIdx.x;
    const int warp = tid >> 5;
    const int lane = tid & 31;
    const int lq  = lane >> 2;
    const int lc  = lane & 3;
    const int lrow = (lane & 7) + ((lane >> 3) & 1) * 8;
    const int lcol = ((lane >> 4) & 1) * 4;

    // plane offsets (words): Kh | Km | Vh | Vm, each double-buffered
    auto plane = [&](int p, int st) { return (uint32_t)((p * 2 + st) * FTW); };

    auto load_kv = [&](int kc, int st) {
        #pragma unroll
        for (int it = 0; it < 2; it++) {
            const int slot = it * 256 + tid;
            const int row = slot >> 3;          // 0..63
            const int c8 = slot & 7;            // 16B chunk
            const uint32_t so = (uint32_t)(row * FST + c8 * 4) * 4u;
            // K tile: rows = keys, cols = this head's 64 dims
            const size_t gk = (size_t)(b * Sseq + kc * 64 + row) * 1024 + h * 64 + c8 * 8;
            cp_async16(sbase + (plane(0, st)) * 4u + so, &Kh[gk]);
            cp_async16(sbase + (plane(1, st)) * 4u + so, &Km[gk]);
            // V^T tile: rows = dims, cols = keys
            const size_t gv = ((size_t)(b * 16 + h) * 64 + row) * 2048 + kc * 64 + c8 * 8;
            cp_async16(sbase + (plane(2, st)) * 4u + so, &Vth[gv]);
            cp_async16(sbase + (plane(3, st)) * 4u + so, &Vtm[gv]);
        }
    };

    load_kv(0, 0);
    cp_commit();

    // Q fragments via direct LDG (packed bf16x2 words)
    const uint32_t* Qh32 = (const uint32_t*)Qh;
    const uint32_t* Qm32 = (const uint32_t*)Qm;
    uint32_t qh[4][4], qm[4][4];
    {
        const int qrow = b * Sseq + t * 128 + warp * 16 + lq;
        const size_t qb0 = (size_t)qrow * 512 + h * 32;
        const size_t qb1 = qb0 + 8 * 512;
        #pragma unroll
        for (int ks = 0; ks < 4; ks++) {
            const int o = ks * 8 + lc;
            qh[ks][0] = Qh32[qb0 + o];     qm[ks][0] = Qm32[qb0 + o];
            qh[ks][1] = Qh32[qb1 + o];     qm[ks][1] = Qm32[qb1 + o];
            qh[ks][2] = Qh32[qb0 + o + 4]; qm[ks][2] = Qm32[qb0 + o + 4];
            qh[ks][3] = Qh32[qb1 + o + 4]; qm[ks][3] = Qm32[qb1 + o + 4];
        }
    }

    float oacc[8][4];
    #pragma unroll
    for (int nt = 0; nt < 8; nt++)
        #pragma unroll
        for (int r = 0; r < 4; r++) oacc[nt][r] = 0.f;
    float m0 = -3.0e38f, m1 = -3.0e38f, l0 = 0.f, l1 = 0.f;

    const int row0 = t * 128 + warp * 16 + lq;
    const int row1 = row0 + 8;
    const int nkc = (t == 0) ? (Sseq / 64) : (2 * t + 2);

    for (int kc = 0; kc < nkc; kc++) {
        cp_wait0();
        __syncthreads();
        if (kc + 1 < nkc) { load_kv(kc + 1, (kc + 1) & 1); cp_commit(); }

        const int st = kc & 1;
        const uint32_t kplh = sbase + plane(0, st) * 4u;
        const uint32_t kplm = sbase + plane(1, st) * 4u;
        const uint32_t vplh = sbase + plane(2, st) * 4u;
        const uint32_t vplm = sbase + plane(3, st) * 4u;

        // ---- S = Q @ K^T (ldmatrix.x4 per nt-pair per plane) ----
        float sacc[8][4];
        #pragma unroll
        for (int nt = 0; nt < 8; nt++)
            #pragma unroll
            for (int r = 0; r < 4; r++) sacc[nt][r] = 0.f;

        #pragma unroll
        for (int ks = 0; ks < 4; ks++) {
            #pragma unroll
            for (int ntp = 0; ntp < 4; ntp++) {
                const uint32_t off =
                    (uint32_t)((ntp * 16 + lrow) * FST + ks * 8 + lcol) * 4u;
                uint32_t h0, h1, h2, h3, w0, w1, w2, w3;
                ldsm_x4(h0, h1, h2, h3, kplh + off);
                ldsm_x4(w0, w1, w2, w3, kplm + off);
                const int n0i = 2 * ntp, n1i = 2 * ntp + 1;
                mma_bf16(sacc[n0i][0], sacc[n0i][1], sacc[n0i][2], sacc[n0i][3],
                         qm[ks][0], qm[ks][1], qm[ks][2], qm[ks][3], h0, h2);
                mma_bf16(sacc[n0i][0], sacc[n0i][1], sacc[n0i][2], sacc[n0i][3],
                         qh[ks][0], qh[ks][1], qh[ks][2], qh[ks][3], w0, w2);
                mma_bf16(sacc[n0i][0], sacc[n0i][1], sacc[n0i][2], sacc[n0i][3],
                         qh[ks][0], qh[ks][1], qh[ks][2], qh[ks][3], h0, h2);
                mma_bf16(sacc[n1i][0], sacc[n1i][1], sacc[n1i][2], sacc[n1i][3],
                         qm[ks][0], qm[ks][1], qm[ks][2], qm[ks][3], h1, h3);
                mma_bf16(sacc[n1i][0], sacc[n1i][1], sacc[n1i][2], sacc[n1i][3],
                         qh[ks][0], qh[ks][1], qh[ks][2], qh[ks][3], w1, w3);
                mma_bf16(sacc[n1i][0], sacc[n1i][1], sacc[n1i][2], sacc[n1i][3],
                         qh[ks][0], qh[ks][1], qh[ks][2], qh[ks][3], h1, h3);
            }
        }

        // ---- mask: z >= s -> -1e12 ----
        #pragma unroll
        for (int nt = 0; nt < 8; nt++) {
            const int cb = kc * 64 + nt * 8 + 2 * lc;
            if (cb     >= row0) sacc[nt][0] = -1.0e12f;
            if (cb + 1 >= row0) sacc[nt][1] = -1.0e12f;
            if (cb     >= row1) sacc[nt][2] = -1.0e12f;
            if (cb + 1 >= row1) sacc[nt][3] = -1.0e12f;
        }

        // ---- online softmax ----
        float mt0 = -3.0e38f, mt1 = -3.0e38f;
        #pragma unroll
        for (int nt = 0; nt < 8; nt++) {
            mt0 = fmaxf(mt0, fmaxf(sacc[nt][0], sacc[nt][1]));
            mt1 = fmaxf(mt1, fmaxf(sacc[nt][2], sacc[nt][3]));
        }
        mt0 = fmaxf(mt0, __shfl_xor_sync(0xffffffffu, mt0, 1));
        mt0 = fmaxf(mt0, __shfl_xor_sync(0xffffffffu, mt0, 2));
        mt1 = fmaxf(mt1, __shfl_xor_sync(0xffffffffu, mt1, 1));
        mt1 = fmaxf(mt1, __shfl_xor_sync(0xffffffffu, mt1, 2));
        const float mn0 = fmaxf(m0, mt0);
        const float mn1 = fmaxf(m1, mt1);
        const float sc0 = __expf(m0 - mn0);
        const float sc1 = __expf(m1 - mn1);
        float ls0 = 0.f, ls1 = 0.f;
        #pragma unroll
        for (int nt = 0; nt < 8; nt++) {
            sacc[nt][0] = __expf(sacc[nt][0] - mn0);
            sacc[nt][1] = __expf(sacc[nt][1] - mn0);
            sacc[nt][2] = __expf(sacc[nt][2] - mn1);
            sacc[nt][3] = __expf(sacc[nt][3] - mn1);
            ls0 += sacc[nt][0] + sacc[nt][1];
            ls1 += sacc[nt][2] + sacc[nt][3];
        }
        l0 = l0 * sc0 + ls0;
        l1 = l1 * sc1 + ls1;
        m0 = mn0; m1 = mn1;
        #pragma unroll
        for (int nt = 0; nt < 8; nt++) {
            oacc[nt][0] *= sc0; oacc[nt][1] *= sc0;
            oacc[nt][2] *= sc1; oacc[nt][3] *= sc1;
        }

        // ---- O += P @ V : P frags straight from sacc registers ----
        #pragma unroll
        for (int ks = 0; ks < 4; ks++) {
            __nv_bfloat16 h0, h1, h2, h3, h4, h5, h6, h7;
            __nv_bfloat16 w0, w1, w2, w3, w4, w5, w6, w7;
            bsplit(sacc[2 * ks][0], h0, w0); bsplit(sacc[2 * ks][1], h1, w1);
            bsplit(sacc[2 * ks][2], h2, w2); bsplit(sacc[2 * ks][3], h3, w3);
            bsplit(sacc[2 * ks + 1][0], h4, w4); bsplit(sacc[2 * ks + 1][1], h5, w5);
            bsplit(sacc[2 * ks + 1][2], h6, w6); bsplit(sacc[2 * ks + 1][3], h7, w7);
            const uint32_t pah0 = bpack(h0, h1), pah1 = bpack(h2, h3);
            const uint32_t pah2 = bpack(h4, h5), pah3 = bpack(h6, h7);
            const uint32_t pam0 = bpack(w0, w1), pam1 = bpack(w2, w3);
            const uint32_t pam2 = bpack(w4, w5), pam3 = bpack(w6, w7);
            #pragma unroll
            for (int ntp = 0; ntp < 4; ntp++) {
                const uint32_t off =
                    (uint32_t)((ntp * 16 + lrow) * FST + ks * 8 + lcol) * 4u;
                uint32_t vh0, vh1, vh2, vh3, vm0, vm1, vm2, vm3;
                ldsm_x4(vh0, vh1, vh2, vh3, vplh + off);
                ldsm_x4(vm0, vm1, vm2, vm3, vplm + off);
                const int n0i = 2 * ntp, n1i = 2 * ntp + 1;
                mma_bf16(oacc[n0i][0], oacc[n0i][1], oacc[n0i][2], oacc[n0i][3],
                         pam0, pam1, pam2, pam3, vh0, vh2);
                mma_bf16(oacc[n0i][0], oacc[n0i][1], oacc[n0i][2], oacc[n0i][3],
                         pah0, pah1, pah2, pah3, vm0, vm2);
                mma_bf16(oacc[n0i][0], oacc[n0i][1], oacc[n0i][2], oacc[n0i][3],
                         pah0, pah1, pah2, pah3, vh0, vh2);
                mma_bf16(oacc[n1i][0], oacc[n1i][1], oacc[n1i][2], oacc[n1i][3],
                         pam0, pam1, pam2, pam3, vh1, vh3);
                mma_bf16(oacc[n1i][0], oacc[n1i][1], oacc[n1i][2], oacc[n1i][3],
                         pah0, pah1, pah2, pah3, vm1, vm3);
                mma_bf16(oacc[n1i][0], oacc[n1i][1], oacc[n1i][2], oacc[n1i][3],
                         pah0, pah1, pah2, pah3, vh1, vh3);
            }
        }
    }

    // ---- epilogue: normalize, split to bf16 planes ----
    l0 += __shfl_xor_sync(0xffffffffu, l0, 1);
    l0 += __shfl_xor_sync(0xffffffffu, l0, 2);
    l1 += __shfl_xor_sync(0xffffffffu, l1, 1);
    l1 += __shfl_xor_sync(0xffffffffu, l1, 2);
    const float inv0 = 1.f / l0;
    const float inv1 = 1.f / l1;

    const size_t ob = ((size_t)(b * Sseq + t * 128 + warp * 16 + lq)) * 1024 + h * 64;
    #pragma unroll
    for (int nt = 0; nt < 8; nt++) {
        const int cb = nt * 8 + 2 * lc;
        float v00 = oacc[nt][0] * inv0, v01 = oacc[nt][1] * inv0;
        float v10 = oacc[nt][2] * inv1, v11 = oacc[nt][3] * inv1;
        __nv_bfloat16 h00, h01, h10, h11, m00, m01, m10, m11;
        bsplit(v00, h00, m00); bsplit(v01, h01, m01);
        bsplit(v10, h10, m10); bsplit(v11, h11, m11);
        *(uint32_t*)&Oh[ob + cb] = bpack(h00, h01);
        *(uint32_t*)&Oh[ob + 8 * 1024 + cb] = bpack(h10, h11);
        *(uint32_t*)&Om[ob + cb] = bpack(m00, m01);
        *(uint32_t*)&Om[ob + 8 * 1024 + cb] = bpack(m10, m11);
    }
}

// ---------------------------------------------------------------------------
extern "C" void kernel_launch(void* const* d_in, const int* in_sizes, int n_in,
                              void* d_out, int out_size)
{
    (void)in_sizes; (void)n_in; (void)out_size;
    const float* attend_from = (const float*)d_in[0];
    const float* attend_to   = (const float*)d_in[1];
    const float* w_q   = (const float*)d_in[2];
    const float* b_q   = (const float*)d_in[3];
    const float* w_kv  = (const float*)d_in[4];
    const float* b_kv  = (const float*)d_in[5];
    const float* w_out = (const float*)d_in[6];
    const float* b_out = (const float*)d_in[7];
    float* out = (float*)d_out;

    __nv_bfloat16 *afh, *afm, *ath, *atm, *wqh, *wqm, *wkvh, *wkvm, *woh, *wom;
    __nv_bfloat16 *qh, *qm, *kh, *km, *vth, *vtm, *oh, *om;
    cudaGetSymbolAddress((void**)&afh, g_Afh);
    cudaGetSymbolAddress((void**)&afm, g_Afm);
    cudaGetSymbolAddress((void**)&ath, g_Ath);
    cudaGetSymbolAddress((void**)&atm, g_Atm);
    cudaGetSymbolAddress((void**)&wqh, g_Wqh);
    cudaGetSymbolAddress((void**)&wqm, g_Wqm);
    cudaGetSymbolAddress((void**)&wkvh, g_Wkvh);
    cudaGetSymbolAddress((void**)&wkvm, g_Wkvm);
    cudaGetSymbolAddress((void**)&woh, g_Woh);
    cudaGetSymbolAddress((void**)&wom, g_Wom);
    cudaGetSymbolAddress((void**)&qh, g_Qh);
    cudaGetSymbolAddress((void**)&qm, g_Qm);
    cudaGetSymbolAddress((void**)&kh, g_Kh);
    cudaGetSymbolAddress((void**)&km, g_Km);
    cudaGetSymbolAddress((void**)&vth, g_Vth);
    cudaGetSymbolAddress((void**)&vtm, g_Vtm);
    cudaGetSymbolAddress((void**)&oh, g_Oh);
    cudaGetSymbolAddress((void**)&om, g_Om);

    cudaFuncSetAttribute(qkv_gemm_kernel,
                         cudaFuncAttributeMaxDynamicSharedMemorySize, GEMM_SMEM);
    cudaFuncSetAttribute(out_gemm_kernel,
                         cudaFuncAttributeMaxDynamicSharedMemorySize, GEMM_SMEM);
    cudaFuncSetAttribute(flash_mma_kernel,
                         cudaFuncAttributeMaxDynamicSharedMemorySize, FLASH_SMEM);

    // 0) pre-split activations, split+transpose weights
    {
        const int nA = Mrows * Fdim / 4;
        asplit_kernel<<<(nA + 255) / 256, 256>>>(attend_from, afh, afm, nA);
        asplit_kernel<<<(nA + 255) / 256, 256>>>(attend_to,   ath, atm, nA);
        wsplit_kernel<<<dim3(32, 32), 256>>>(w_q,   wqh,  wqm,  1024, 1024);
        wsplit_kernel<<<dim3(32, 64), 256>>>(w_kv,  wkvh, wkvm, 1024, 2048);
        wsplit_kernel<<<dim3(32, 32), 256>>>(w_out, woh,  wom,  1024, 1024);
    }

    // 1) merged Q + KV projection
    qkv_gemm_kernel<<<768, 256, GEMM_SMEM>>>(
        afh, afm, ath, atm, wqh, wqm, wkvh, wkvm, b_q, b_kv,
        qh, qm, kh, km, vth, vtm);

    // 2) flash attention
    {
        dim3 grid(Sseq / 128, Hh, Bsz);
        flash_mma_kernel<<<grid, 256, FLASH_SMEM>>>(
            qh, qm, kh, km, vth, vtm, oh, om);
    }

    // 3) output projection
    {
        dim3 grid(Fdim / 128, Mrows / 128);
        out_gemm_kernel<<<grid, 256, GEMM_SMEM>>>(oh, om, woh, wom, b_out, out);
    }
}

// round 10
// speedup vs baseline: 1.0929x; 1.0929x over previous
#include <cuda_runtime.h>
#include <cuda_bf16.h>
#include <math.h>
#include <stdint.h>

// Problem constants (fixed shapes)
constexpr int Bsz  = 2;
constexpr int Sseq = 2048;
constexpr int Fdim = 1024;
constexpr int Hh   = 16;
constexpr int Dh   = 64;
constexpr int Mrows = Bsz * Sseq;   // 4096

// Scratch (device globals, allocation-free). All operands live as TWO bf16
// planes: hi = bf16(x), mid = bf16(x - hi). hi+mid recovers fp32 to ~2^-16.
__device__ __nv_bfloat16 g_Afh[(size_t)Mrows * Fdim];  // attend_from planes
__device__ __nv_bfloat16 g_Afm[(size_t)Mrows * Fdim];
__device__ __nv_bfloat16 g_Ath[(size_t)Mrows * Fdim];  // attend_to planes
__device__ __nv_bfloat16 g_Atm[(size_t)Mrows * Fdim];
__device__ __nv_bfloat16 g_Wqh[(size_t)Fdim * Fdim];   // w_q^T  [n][k]
__device__ __nv_bfloat16 g_Wqm[(size_t)Fdim * Fdim];
__device__ __nv_bfloat16 g_Wkvh[(size_t)2 * Fdim * Fdim]; // w_kv^T [n][k]
__device__ __nv_bfloat16 g_Wkvm[(size_t)2 * Fdim * Fdim];
__device__ __nv_bfloat16 g_Woh[(size_t)Fdim * Fdim];   // w_out^T [n][k]
__device__ __nv_bfloat16 g_Wom[(size_t)Fdim * Fdim];
__device__ __nv_bfloat16 g_Qh[(size_t)Mrows * Fdim];   // Q planes [row][d]
__device__ __nv_bfloat16 g_Qm[(size_t)Mrows * Fdim];
__device__ __nv_bfloat16 g_Kh[(size_t)Mrows * Fdim];   // K planes [row][d]
__device__ __nv_bfloat16 g_Km[(size_t)Mrows * Fdim];
__device__ __nv_bfloat16 g_Vth[(size_t)Mrows * Fdim];  // V^T planes [b][h][d][s]
__device__ __nv_bfloat16 g_Vtm[(size_t)Mrows * Fdim];
__device__ __nv_bfloat16 g_Oh[(size_t)Mrows * Fdim];   // O planes [row][feat]
__device__ __nv_bfloat16 g_Om[(size_t)Mrows * Fdim];

// ---------------------------------------------------------------------------
// PTX helpers
// ---------------------------------------------------------------------------
__device__ __forceinline__ void cp_async16(uint32_t saddr, const void* gptr) {
    asm volatile("cp.async.cg.shared.global [%0], [%1], 16;"
                 :: "r"(saddr), "l"(gptr));
}
__device__ __forceinline__ void cp_commit() {
    asm volatile("cp.async.commit_group;");
}
__device__ __forceinline__ void cp_wait0() {
    asm volatile("cp.async.wait_group 0;");
}

__device__ __forceinline__ void mma_bf16(
    float& d0, float& d1, float& d2, float& d3,
    uint32_t a0, uint32_t a1, uint32_t a2, uint32_t a3,
    uint32_t b0, uint32_t b1)
{
    asm volatile(
        "mma.sync.aligned.m16n8k16.row.col.f32.bf16.bf16.f32 "
        "{%0,%1,%2,%3},{%4,%5,%6,%7},{%8,%9},{%0,%1,%2,%3};"
        : "+f"(d0), "+f"(d1), "+f"(d2), "+f"(d3)
        : "r"(a0), "r"(a1), "r"(a2), "r"(a3), "r"(b0), "r"(b1));
}

__device__ __forceinline__ void bsplit(float v, __nv_bfloat16& h, __nv_bfloat16& m) {
    h = __float2bfloat16_rn(v);
    m = __float2bfloat16_rn(v - __bfloat162float(h));
}
__device__ __forceinline__ uint32_t bpack(__nv_bfloat16 lo, __nv_bfloat16 hi) {
    __nv_bfloat162 t;
    t.x = lo; t.y = hi;            // .x = low half = lower k index
    return *reinterpret_cast<uint32_t*>(&t);
}

// ---------------------------------------------------------------------------
// Pre-pass: elementwise split (no transpose) for activations [M][K].
// ---------------------------------------------------------------------------
__global__ __launch_bounds__(256) void asplit_kernel(
    const float* __restrict__ src, __nv_bfloat16* __restrict__ hi,
    __nv_bfloat16* __restrict__ mid, int n4)
{
    const int i = blockIdx.x * 256 + threadIdx.x;
    if (i >= n4) return;
    float4 v = ((const float4*)src)[i];
    __nv_bfloat16 h0, h1, h2, h3, m0, m1, m2, m3;
    bsplit(v.x, h0, m0); bsplit(v.y, h1, m1);
    bsplit(v.z, h2, m2); bsplit(v.w, h3, m3);
    uint2 hw = make_uint2(bpack(h0, h1), bpack(h2, h3));
    uint2 mw = make_uint2(bpack(m0, m1), bpack(m2, m3));
    ((uint2*)hi)[i] = hw;
    ((uint2*)mid)[i] = mw;
}

// Pre-pass: split + transpose weights w[k][n] -> planes [n][k].
__global__ __launch_bounds__(256) void wsplit_kernel(
    const float* __restrict__ w, __nv_bfloat16* __restrict__ th,
    __nv_bfloat16* __restrict__ tm, int K, int N)
{
    __shared__ float ts[32][33];
    const int k0 = blockIdx.x * 32;
    const int n0 = blockIdx.y * 32;
    const int tx = threadIdx.x & 31;
    const int ty = threadIdx.x >> 5;     // 0..7
    #pragma unroll
    for (int i = 0; i < 4; i++)
        ts[ty + 8 * i][tx] = w[(size_t)(k0 + ty + 8 * i) * N + n0 + tx];
    __syncthreads();
    #pragma unroll
    for (int i = 0; i < 4; i++) {
        float v = ts[tx][ty + 8 * i];
        __nv_bfloat16 h, m;
        bsplit(v, h, m);
        const size_t o = (size_t)(n0 + ty + 8 * i) * K + k0 + tx;
        th[o] = h;
        tm[o] = m;
    }
}

// ---------------------------------------------------------------------------
// Row-0 fix: reference row s=0 is fully masked (uniform softmax over all Z)
// -> O[b, 0, :] = mean over s of V. Computed exactly in fp32 from V^T planes.
// grid = (1024 feats, Bsz); 256 threads reduce 2048 elements.
// ---------------------------------------------------------------------------
__global__ __launch_bounds__(256) void row0_kernel(
    const __nv_bfloat16* __restrict__ Vth, const __nv_bfloat16* __restrict__ Vtm,
    __nv_bfloat16* __restrict__ Oh, __nv_bfloat16* __restrict__ Om)
{
    __shared__ float red[256];
    const int f = blockIdx.x;            // feature 0..1023
    const int b = blockIdx.y;
    const int h = f >> 6, d = f & 63;
    const size_t base = ((size_t)(b * 16 + h) * 64 + d) * 2048;
    float s = 0.f;
    for (int i = threadIdx.x; i < 2048; i += 256)
        s += __bfloat162float(Vth[base + i]) + __bfloat162float(Vtm[base + i]);
    red[threadIdx.x] = s;
    __syncthreads();
    for (int o = 128; o > 0; o >>= 1) {
        if (threadIdx.x < o) red[threadIdx.x] += red[threadIdx.x + o];
        __syncthreads();
    }
    if (threadIdx.x == 0) {
        const float v = red[0] * (1.f / 2048.f);
        __nv_bfloat16 hh, mm;
        bsplit(v, hh, mm);
        const size_t o = (size_t)(b * Sseq) * 1024 + f;
        Oh[o] = hh;
        Om[o] = mm;
    }
}

// ---------------------------------------------------------------------------
// bf16x3 GEMM core: C[M,N] = A[M,1024] @ W^T[n][k] (+bias via epilogue).
// 128x128 block tile, BK=32, 256 threads, 8 warps of 64x32 warp tiles.
// Hot loop: pure LDS + HMMA (3 MMAs per m16n8k16 pair: am*bh, ah*bm, ah*bh).
// One __syncthreads per k-tile (top barrier covers the WAR hazard).
// ---------------------------------------------------------------------------
constexpr int SW  = 20;                    // words per row (16 data + 4 pad)
constexpr int PLW = 128 * SW;              // 2560 words per plane
constexpr int STAGE_W = 4 * PLW;           // 10240 words per stage
constexpr int GEMM_SMEM = 2 * STAGE_W * 4; // 81920 B

template <typename EPI>
__device__ __forceinline__ void gemm_mainloop(
    const __nv_bfloat16* __restrict__ Ah, const __nv_bfloat16* __restrict__ Am,
    const __nv_bfloat16* __restrict__ Bh, const __nv_bfloat16* __restrict__ Bm,
    int m0, int n0, uint32_t* smw, EPI epi)
{
    const uint32_t sbase = (uint32_t)__cvta_generic_to_shared(smw);
    const int tid  = threadIdx.x;
    const int warp = tid >> 5;
    const int lane = tid & 31;
    const int rbase = (warp & 1) * 64;
    const int cbase = (warp >> 1) * 32;
    const int lq  = lane >> 2;      // 0..7
    const int lc  = lane & 3;       // 0..3

    float acc[4][4][4];
    #pragma unroll
    for (int i = 0; i < 4; i++)
        #pragma unroll
        for (int j = 0; j < 4; j++)
            #pragma unroll
            for (int r = 0; r < 4; r++) acc[i][j][r] = 0.f;

    auto load_tile = [&](int kt, int st) {
        const int k0 = kt * 32;
        const uint32_t base = sbase + (uint32_t)(st * STAGE_W) * 4u;
        #pragma unroll
        for (int it = 0; it < 2; it++) {
            const int slot = it * 256 + tid;
            const int row = slot >> 2, c4 = slot & 3;
            const uint32_t so = (uint32_t)(row * SW + c4 * 4) * 4u;
            const size_t ga = (size_t)(m0 + row) * 1024 + k0 + c4 * 8;
            const size_t gb = (size_t)(n0 + row) * 1024 + k0 + c4 * 8;
            cp_async16(base + so, &Ah[ga]);
            cp_async16(base + (uint32_t)(PLW * 4) + so, &Am[ga]);
            cp_async16(base + (uint32_t)(2 * PLW * 4) + so, &Bh[gb]);
            cp_async16(base + (uint32_t)(3 * PLW * 4) + so, &Bm[gb]);
        }
    };

    load_tile(0, 0);
    cp_commit();

    for (int kt = 0; kt < 32; kt++) {
        cp_wait0();
        __syncthreads();   // also orders compute(kt-1) before loads(kt+1)
        if (kt + 1 < 32) { load_tile(kt + 1, (kt + 1) & 1); cp_commit(); }

        const uint32_t* AH = smw + (kt & 1) * STAGE_W;
        const uint32_t* AM = AH + PLW;
        const uint32_t* BH = AH + 2 * PLW;
        const uint32_t* BM = AH + 3 * PLW;

        #pragma unroll
        for (int ks = 0; ks < 2; ks++) {
            const int kk2 = ks * 8;
            uint32_t ah[4][4], am[4][4], bh[4][2], bm[4][2];
            #pragma unroll
            for (int mi = 0; mi < 4; mi++) {
                const int rr = rbase + mi * 16 + lq;
                const int o0 = rr * SW + kk2 + lc;
                const int o1 = (rr + 8) * SW + kk2 + lc;
                ah[mi][0] = AH[o0];     am[mi][0] = AM[o0];
                ah[mi][1] = AH[o1];     am[mi][1] = AM[o1];
                ah[mi][2] = AH[o0 + 4]; am[mi][2] = AM[o0 + 4];
                ah[mi][3] = AH[o1 + 4]; am[mi][3] = AM[o1 + 4];
            }
            #pragma unroll
            for (int nj = 0; nj < 4; nj++) {
                const int cc = cbase + nj * 8 + lq;
                const int o = cc * SW + kk2 + lc;
                bh[nj][0] = BH[o];     bm[nj][0] = BM[o];
                bh[nj][1] = BH[o + 4]; bm[nj][1] = BM[o + 4];
            }
            #pragma unroll
            for (int mi = 0; mi < 4; mi++)
                #pragma unroll
                for (int nj = 0; nj < 4; nj++) {
                    mma_bf16(acc[mi][nj][0], acc[mi][nj][1],
                             acc[mi][nj][2], acc[mi][nj][3],
                             am[mi][0], am[mi][1], am[mi][2], am[mi][3],
                             bh[nj][0], bh[nj][1]);
                    mma_bf16(acc[mi][nj][0], acc[mi][nj][1],
                             acc[mi][nj][2], acc[mi][nj][3],
                             ah[mi][0], ah[mi][1], ah[mi][2], ah[mi][3],
                             bm[nj][0], bm[nj][1]);
                    mma_bf16(acc[mi][nj][0], acc[mi][nj][1],
                             acc[mi][nj][2], acc[mi][nj][3],
                             ah[mi][0], ah[mi][1], ah[mi][2], ah[mi][3],
                             bh[nj][0], bh[nj][1]);
                }
        }
    }
    __syncthreads();   // final: all reads done before epilogue reuses nothing; harmless
    epi(acc, rbase, cbase, lq, lc);
}

// Merged Q + KV projection. grid.x = 768.
//  bx <  256: Q tile -> (g_Qh, g_Qm)
//  bx >= 256: KV tile -> K planes or V^T planes
__global__ __launch_bounds__(256, 2) void qkv_gemm_kernel(
    const __nv_bfloat16* __restrict__ Afh, const __nv_bfloat16* __restrict__ Afm,
    const __nv_bfloat16* __restrict__ Ath, const __nv_bfloat16* __restrict__ Atm,
    const __nv_bfloat16* __restrict__ Wqh, const __nv_bfloat16* __restrict__ Wqm,
    const __nv_bfloat16* __restrict__ Wkvh, const __nv_bfloat16* __restrict__ Wkvm,
    const float* __restrict__ bq, const float* __restrict__ bkv,
    __nv_bfloat16* __restrict__ Qh, __nv_bfloat16* __restrict__ Qm,
    __nv_bfloat16* __restrict__ Kh, __nv_bfloat16* __restrict__ Km,
    __nv_bfloat16* __restrict__ Vth, __nv_bfloat16* __restrict__ Vtm)
{
    extern __shared__ uint32_t smw[];
    const int bx = blockIdx.x;

    const __nv_bfloat16 *Ah, *Am, *Bh, *Bm;
    const float* bias;
    int m0, n0, is_v = 0, ncol;
    if (bx < 256) {
        Ah = Afh; Am = Afm; Bh = Wqh; Bm = Wqm; bias = bq;
        m0 = (bx >> 3) * 128; n0 = (bx & 7) * 128; ncol = n0;
    } else {
        const int bxx = bx - 256;
        Ah = Ath; Am = Atm; Bh = Wkvh; Bm = Wkvm; bias = bkv;
        m0 = (bxx >> 4) * 128; n0 = (bxx & 15) * 128;
        if (n0 < 1024) { ncol = n0; }
        else           { ncol = n0 - 1024; is_v = 1; }
    }

    gemm_mainloop(Ah, Am, Bh, Bm, m0, n0, smw,
        [&](float (&acc)[4][4][4], int rbase, int cbase, int lq, int lc) {
            #pragma unroll
            for (int mi = 0; mi < 4; mi++) {
                const int r0 = m0 + rbase + mi * 16 + lq;
                #pragma unroll
                for (int nj = 0; nj < 4; nj++) {
                    const int col = ncol + cbase + nj * 8 + lc * 2;
                    const float b0 = bias[n0 - ncol + col];
                    const float b1 = bias[n0 - ncol + col + 1];
                    float v00 = acc[mi][nj][0] + b0;
                    float v01 = acc[mi][nj][1] + b1;
                    float v10 = acc[mi][nj][2] + b0;
                    float v11 = acc[mi][nj][3] + b1;
                    __nv_bfloat16 h00, h01, h10, h11, q00, q01, q10, q11;
                    bsplit(v00, h00, q00); bsplit(v01, h01, q01);
                    bsplit(v10, h10, q10); bsplit(v11, h11, q11);
                    if (!is_v) {
                        __nv_bfloat16* Dh = (bx < 256) ? Qh : Kh;
                        __nv_bfloat16* Dm = (bx < 256) ? Qm : Km;
                        const size_t o0 = (size_t)r0 * 1024 + col;
                        const size_t o1 = (size_t)(r0 + 8) * 1024 + col;
                        *(uint32_t*)&Dh[o0] = bpack(h00, h01);
                        *(uint32_t*)&Dh[o1] = bpack(h10, h11);
                        *(uint32_t*)&Dm[o0] = bpack(q00, q01);
                        *(uint32_t*)&Dm[o1] = bpack(q10, q11);
                    } else {
                        // V transposed: [b][h][d][s]
                        const int h = col >> 6, d = col & 63;
                        const int bl0 = r0 >> 11, s0 = r0 & 2047;
                        const int bl1 = (r0 + 8) >> 11, s1 = (r0 + 8) & 2047;
                        const size_t i00 = ((size_t)(bl0 * 16 + h) * 64 + d) * 2048 + s0;
                        const size_t i10 = ((size_t)(bl1 * 16 + h) * 64 + d) * 2048 + s1;
                        Vth[i00] = h00;          Vtm[i00] = q00;
                        Vth[i00 + 2048] = h01;   Vtm[i00 + 2048] = q01;
                        Vth[i10] = h10;          Vtm[i10] = q10;
                        Vth[i10 + 2048] = h11;   Vtm[i10 + 2048] = q11;
                    }
                }
            }
        });
}

// Output projection: out = O @ w_out + b_out (fp32 store).
__global__ __launch_bounds__(256, 2) void out_gemm_kernel(
    const __nv_bfloat16* __restrict__ Ah, const __nv_bfloat16* __restrict__ Am,
    const __nv_bfloat16* __restrict__ Bh, const __nv_bfloat16* __restrict__ Bm,
    const float* __restrict__ bias, float* __restrict__ C)
{
    extern __shared__ uint32_t smw[];
    const int m0 = blockIdx.y * 128;
    const int n0 = blockIdx.x * 128;
    gemm_mainloop(Ah, Am, Bh, Bm, m0, n0, smw,
        [&](float (&acc)[4][4][4], int rbase, int cbase, int lq, int lc) {
            #pragma unroll
            for (int mi = 0; mi < 4; mi++) {
                const int r0 = m0 + rbase + mi * 16 + lq;
                #pragma unroll
                for (int nj = 0; nj < 4; nj++) {
                    const int col = n0 + cbase + nj * 8 + lc * 2;
                    const float b0 = bias[col], b1 = bias[col + 1];
                    *(float2*)&C[(size_t)r0 * Fdim + col] =
                        make_float2(acc[mi][nj][0] + b0, acc[mi][nj][1] + b1);
                    *(float2*)&C[(size_t)(r0 + 8) * Fdim + col] =
                        make_float2(acc[mi][nj][2] + b0, acc[mi][nj][3] + b1);
                }
            }
        });
}

// ---------------------------------------------------------------------------
// bf16x3 flash attention. Br=128, Bc=64, d=64. 8 warps, 16 q-rows each.
// Q frags via direct LDG (once). K tiles [key][d], V^T tiles [d][key] via
// cp.async double-buffered. S: 3 MMAs/pair; O: 3 MMAs/pair with P frags
// built directly from S-accumulator registers (no smem staging).
// Mask: z >= s -> -1e12f. CTA t does 2t+2 kv tiles; row s=0 is fixed up
// separately by row0_kernel (uniform softmax = mean of V).
// ---------------------------------------------------------------------------
constexpr int FST   = 36;                 // tile row stride in words
constexpr int FTW   = 64 * FST;           // 2304 words per plane-stage
constexpr int FLASH_SMEM = 8 * FTW * 4;   // 4 planes x 2 stages = 73728 B

__global__ __launch_bounds__(256) void flash_mma_kernel(
    const __nv_bfloat16* __restrict__ Qh, const __nv_bfloat16* __restrict__ Qm,
    const __nv_bfloat16* __restrict__ Kh, const __nv_bfloat16* __restrict__ Km,
    const __nv_bfloat16* __restrict__ Vth, const __nv_bfloat16* __restrict__ Vtm,
    __nv_bfloat16* __restrict__ Oh, __nv_bfloat16* __restrict__ Om)
{
    extern __shared__ uint32_t smw[];
    const uint32_t sbase = (uint32_t)__cvta_generic_to_shared(smw);

    const int t = 15 - (int)blockIdx.x;        // heavy CTAs first
    const int h = blockIdx.y;
    const int b = blockIdx.z;
    const int tid  = threadIdx.x;
    const int warp = tid >> 5;
    const int lane = tid & 31;
    const int lq  = lane >> 2;
    const int lc  = lane & 3;

    // plane offsets (words): Kh | Km | Vh | Vm, each double-buffered
    auto plane = [&](int p, int st) { return (uint32_t)((p * 2 + st) * FTW); };

    auto load_kv = [&](int kc, int st) {
        #pragma unroll
        for (int it = 0; it < 2; it++) {
            const int slot = it * 256 + tid;
            const int row = slot >> 3;          // 0..63
            const int c8 = slot & 7;            // 16B chunk
            const uint32_t so = (uint32_t)(row * FST + c8 * 4) * 4u;
            // K tile: rows = keys, cols = this head's 64 dims
            const size_t gk = (size_t)(b * Sseq + kc * 64 + row) * 1024 + h * 64 + c8 * 8;
            cp_async16(sbase + (plane(0, st)) * 4u + so, &Kh[gk]);
            cp_async16(sbase + (plane(1, st)) * 4u + so, &Km[gk]);
            // V^T tile: rows = dims, cols = keys
            const size_t gv = ((size_t)(b * 16 + h) * 64 + row) * 2048 + kc * 64 + c8 * 8;
            cp_async16(sbase + (plane(2, st)) * 4u + so, &Vth[gv]);
            cp_async16(sbase + (plane(3, st)) * 4u + so, &Vtm[gv]);
        }
    };

    load_kv(0, 0);
    cp_commit();

    // Q fragments via direct LDG (packed bf16x2 words)
    const uint32_t* Qh32 = (const uint32_t*)Qh;
    const uint32_t* Qm32 = (const uint32_t*)Qm;
    uint32_t qh[4][4], qm[4][4];
    {
        const int qrow = b * Sseq + t * 128 + warp * 16 + lq;
        const size_t qb0 = (size_t)qrow * 512 + h * 32;
        const size_t qb1 = qb0 + 8 * 512;
        #pragma unroll
        for (int ks = 0; ks < 4; ks++) {
            const int o = ks * 8 + lc;
            qh[ks][0] = Qh32[qb0 + o];     qm[ks][0] = Qm32[qb0 + o];
            qh[ks][1] = Qh32[qb1 + o];     qm[ks][1] = Qm32[qb1 + o];
            qh[ks][2] = Qh32[qb0 + o + 4]; qm[ks][2] = Qm32[qb0 + o + 4];
            qh[ks][3] = Qh32[qb1 + o + 4]; qm[ks][3] = Qm32[qb1 + o + 4];
        }
    }

    float oacc[8][4];
    #pragma unroll
    for (int nt = 0; nt < 8; nt++)
        #pragma unroll
        for (int r = 0; r < 4; r++) oacc[nt][r] = 0.f;
    float m0 = -3.0e38f, m1 = -3.0e38f, l0 = 0.f, l1 = 0.f;

    const int row0 = t * 128 + warp * 16 + lq;
    const int row1 = row0 + 8;
    const int nkc = 2 * t + 2;

    for (int kc = 0; kc < nkc; kc++) {
        cp_wait0();
        __syncthreads();
        if (kc + 1 < nkc) { load_kv(kc + 1, (kc + 1) & 1); cp_commit(); }

        const int st = kc & 1;
        const uint32_t* KH = smw + plane(0, st);
        const uint32_t* KM = smw + plane(1, st);
        const uint32_t* VH = smw + plane(2, st);
        const uint32_t* VM = smw + plane(3, st);

        // ---- S = Q @ K^T ----
        float sacc[8][4];
        #pragma unroll
        for (int nt = 0; nt < 8; nt++)
            #pragma unroll
            for (int r = 0; r < 4; r++) sacc[nt][r] = 0.f;

        #pragma unroll
        for (int ks = 0; ks < 4; ks++) {
            #pragma unroll
            for (int nt = 0; nt < 8; nt++) {
                const int ko = (nt * 8 + lq) * FST + ks * 8 + lc;
                const uint32_t bh0 = KH[ko], bh1 = KH[ko + 4];
                const uint32_t bm0 = KM[ko], bm1 = KM[ko + 4];
                mma_bf16(sacc[nt][0], sacc[nt][1], sacc[nt][2], sacc[nt][3],
                         qm[ks][0], qm[ks][1], qm[ks][2], qm[ks][3], bh0, bh1);
                mma_bf16(sacc[nt][0], sacc[nt][1], sacc[nt][2], sacc[nt][3],
                         qh[ks][0], qh[ks][1], qh[ks][2], qh[ks][3], bm0, bm1);
                mma_bf16(sacc[nt][0], sacc[nt][1], sacc[nt][2], sacc[nt][3],
                         qh[ks][0], qh[ks][1], qh[ks][2], qh[ks][3], bh0, bh1);
            }
        }

        // ---- mask: z >= s -> -1e12 ----
        #pragma unroll
        for (int nt = 0; nt < 8; nt++) {
            const int cb = kc * 64 + nt * 8 + 2 * lc;
            if (cb     >= row0) sacc[nt][0] = -1.0e12f;
            if (cb + 1 >= row0) sacc[nt][1] = -1.0e12f;
            if (cb     >= row1) sacc[nt][2] = -1.0e12f;
            if (cb + 1 >= row1) sacc[nt][3] = -1.0e12f;
        }

        // ---- online softmax ----
        float mt0 = -3.0e38f, mt1 = -3.0e38f;
        #pragma unroll
        for (int nt = 0; nt < 8; nt++) {
            mt0 = fmaxf(mt0, fmaxf(sacc[nt][0], sacc[nt][1]));
            mt1 = fmaxf(mt1, fmaxf(sacc[nt][2], sacc[nt][3]));
        }
        mt0 = fmaxf(mt0, __shfl_xor_sync(0xffffffffu, mt0, 1));
        mt0 = fmaxf(mt0, __shfl_xor_sync(0xffffffffu, mt0, 2));
        mt1 = fmaxf(mt1, __shfl_xor_sync(0xffffffffu, mt1, 1));
        mt1 = fmaxf(mt1, __shfl_xor_sync(0xffffffffu, mt1, 2));
        const float mn0 = fmaxf(m0, mt0);
        const float mn1 = fmaxf(m1, mt1);
        const float sc0 = __expf(m0 - mn0);
        const float sc1 = __expf(m1 - mn1);
        float ls0 = 0.f, ls1 = 0.f;
        #pragma unroll
        for (int nt = 0; nt < 8; nt++) {
            sacc[nt][0] = __expf(sacc[nt][0] - mn0);
            sacc[nt][1] = __expf(sacc[nt][1] - mn0);
            sacc[nt][2] = __expf(sacc[nt][2] - mn1);
            sacc[nt][3] = __expf(sacc[nt][3] - mn1);
            ls0 += sacc[nt][0] + sacc[nt][1];
            ls1 += sacc[nt][2] + sacc[nt][3];
        }
        l0 = l0 * sc0 + ls0;
        l1 = l1 * sc1 + ls1;
        m0 = mn0; m1 = mn1;
        #pragma unroll
        for (int nt = 0; nt < 8; nt++) {
            oacc[nt][0] *= sc0; oacc[nt][1] *= sc0;
            oacc[nt][2] *= sc1; oacc[nt][3] *= sc1;
        }

        // ---- O += P @ V : P frags straight from sacc registers ----
        #pragma unroll
        for (int ks = 0; ks < 4; ks++) {
            __nv_bfloat16 h0, h1, h2, h3, h4, h5, h6, h7;
            __nv_bfloat16 w0, w1, w2, w3, w4, w5, w6, w7;
            bsplit(sacc[2 * ks][0], h0, w0); bsplit(sacc[2 * ks][1], h1, w1);
            bsplit(sacc[2 * ks][2], h2, w2); bsplit(sacc[2 * ks][3], h3, w3);
            bsplit(sacc[2 * ks + 1][0], h4, w4); bsplit(sacc[2 * ks + 1][1], h5, w5);
            bsplit(sacc[2 * ks + 1][2], h6, w6); bsplit(sacc[2 * ks + 1][3], h7, w7);
            const uint32_t pah0 = bpack(h0, h1), pah1 = bpack(h2, h3);
            const uint32_t pah2 = bpack(h4, h5), pah3 = bpack(h6, h7);
            const uint32_t pam0 = bpack(w0, w1), pam1 = bpack(w2, w3);
            const uint32_t pam2 = bpack(w4, w5), pam3 = bpack(w6, w7);
            #pragma unroll
            for (int nt = 0; nt < 8; nt++) {
                const int vo = (nt * 8 + lq) * FST + ks * 8 + lc;
                const uint32_t vh0 = VH[vo], vh1 = VH[vo + 4];
                const uint32_t vm0 = VM[vo], vm1 = VM[vo + 4];
                mma_bf16(oacc[nt][0], oacc[nt][1], oacc[nt][2], oacc[nt][3],
                         pam0, pam1, pam2, pam3, vh0, vh1);
                mma_bf16(oacc[nt][0], oacc[nt][1], oacc[nt][2], oacc[nt][3],
                         pah0, pah1, pah2, pah3, vm0, vm1);
                mma_bf16(oacc[nt][0], oacc[nt][1], oacc[nt][2], oacc[nt][3],
                         pah0, pah1, pah2, pah3, vh0, vh1);
            }
        }
    }

    // ---- epilogue: normalize, split to bf16 planes ----
    l0 += __shfl_xor_sync(0xffffffffu, l0, 1);
    l0 += __shfl_xor_sync(0xffffffffu, l0, 2);
    l1 += __shfl_xor_sync(0xffffffffu, l1, 1);
    l1 += __shfl_xor_sync(0xffffffffu, l1, 2);
    const float inv0 = 1.f / l0;
    const float inv1 = 1.f / l1;

    const size_t ob = ((size_t)(b * Sseq + t * 128 + warp * 16 + lq)) * 1024 + h * 64;
    #pragma unroll
    for (int nt = 0; nt < 8; nt++) {
        const int cb = nt * 8 + 2 * lc;
        float v00 = oacc[nt][0] * inv0, v01 = oacc[nt][1] * inv0;
        float v10 = oacc[nt][2] * inv1, v11 = oacc[nt][3] * inv1;
        __nv_bfloat16 h00, h01, h10, h11, m00, m01, m10, m11;
        bsplit(v00, h00, m00); bsplit(v01, h01, m01);
        bsplit(v10, h10, m10); bsplit(v11, h11, m11);
        *(uint32_t*)&Oh[ob + cb] = bpack(h00, h01);
        *(uint32_t*)&Oh[ob + 8 * 1024 + cb] = bpack(h10, h11);
        *(uint32_t*)&Om[ob + cb] = bpack(m00, m01);
        *(uint32_t*)&Om[ob + 8 * 1024 + cb] = bpack(m10, m11);
    }
}

// ---------------------------------------------------------------------------
extern "C" void kernel_launch(void* const* d_in, const int* in_sizes, int n_in,
                              void* d_out, int out_size)
{
    (void)in_sizes; (void)n_in; (void)out_size;
    const float* attend_from = (const float*)d_in[0];
    const float* attend_to   = (const float*)d_in[1];
    const float* w_q   = (const float*)d_in[2];
    const float* b_q   = (const float*)d_in[3];
    const float* w_kv  = (const float*)d_in[4];
    const float* b_kv  = (const float*)d_in[5];
    const float* w_out = (const float*)d_in[6];
    const float* b_out = (const float*)d_in[7];
    float* out = (float*)d_out;

    __nv_bfloat16 *afh, *afm, *ath, *atm, *wqh, *wqm, *wkvh, *wkvm, *woh, *wom;
    __nv_bfloat16 *qh, *qm, *kh, *km, *vth, *vtm, *oh, *om;
    cudaGetSymbolAddress((void**)&afh, g_Afh);
    cudaGetSymbolAddress((void**)&afm, g_Afm);
    cudaGetSymbolAddress((void**)&ath, g_Ath);
    cudaGetSymbolAddress((void**)&atm, g_Atm);
    cudaGetSymbolAddress((void**)&wqh, g_Wqh);
    cudaGetSymbolAddress((void**)&wqm, g_Wqm);
    cudaGetSymbolAddress((void**)&wkvh, g_Wkvh);
    cudaGetSymbolAddress((void**)&wkvm, g_Wkvm);
    cudaGetSymbolAddress((void**)&woh, g_Woh);
    cudaGetSymbolAddress((void**)&wom, g_Wom);
    cudaGetSymbolAddress((void**)&qh, g_Qh);
    cudaGetSymbolAddress((void**)&qm, g_Qm);
    cudaGetSymbolAddress((void**)&kh, g_Kh);
    cudaGetSymbolAddress((void**)&km, g_Km);
    cudaGetSymbolAddress((void**)&vth, g_Vth);
    cudaGetSymbolAddress((void**)&vtm, g_Vtm);
    cudaGetSymbolAddress((void**)&oh, g_Oh);
    cudaGetSymbolAddress((void**)&om, g_Om);

    cudaFuncSetAttribute(qkv_gemm_kernel,
                         cudaFuncAttributeMaxDynamicSharedMemorySize, GEMM_SMEM);
    cudaFuncSetAttribute(out_gemm_kernel,
                         cudaFuncAttributeMaxDynamicSharedMemorySize, GEMM_SMEM);
    cudaFuncSetAttribute(flash_mma_kernel,
                         cudaFuncAttributeMaxDynamicSharedMemorySize, FLASH_SMEM);

    // 0) pre-split activations, split+transpose weights
    {
        const int nA = Mrows * Fdim / 4;
        asplit_kernel<<<(nA + 255) / 256, 256>>>(attend_from, afh, afm, nA);
        asplit_kernel<<<(nA + 255) / 256, 256>>>(attend_to,   ath, atm, nA);
        wsplit_kernel<<<dim3(32, 32), 256>>>(w_q,   wqh,  wqm,  1024, 1024);
        wsplit_kernel<<<dim3(32, 64), 256>>>(w_kv,  wkvh, wkvm, 1024, 2048);
        wsplit_kernel<<<dim3(32, 32), 256>>>(w_out, woh,  wom,  1024, 1024);
    }

    // 1) merged Q + KV projection
    qkv_gemm_kernel<<<768, 256, GEMM_SMEM>>>(
        afh, afm, ath, atm, wqh, wqm, wkvh, wkvm, b_q, b_kv,
        qh, qm, kh, km, vth, vtm);

    // 2) flash attention (row s=0 handled by row0_kernel)
    {
        dim3 grid(Sseq / 128, Hh, Bsz);
        flash_mma_kernel<<<grid, 256, FLASH_SMEM>>>(
            qh, qm, kh, km, vth, vtm, oh, om);
    }

    // 2b) exact fix-up for fully-masked row s=0: O = mean over s of V
    {
        dim3 grid(1024, Bsz);
        row0_kernel<<<grid, 256>>>(vth, vtm, oh, om);
    }

    // 3) output projection
    {
        dim3 grid(Fdim / 128, Mrows / 128);
        out_gemm_kernel<<<grid, 256, GEMM_SMEM>>>(oh, om, woh, wom, b_out, out);
    }
}

// round 12
// speedup vs baseline: 1.1045x; 1.0106x over previous
#include <cuda_runtime.h>
#include <cuda_bf16.h>
#include <math.h>
#include <stdint.h>

// Problem constants (fixed shapes)
constexpr int Bsz  = 2;
constexpr int Sseq = 2048;
constexpr int Fdim = 1024;
constexpr int Hh   = 16;
constexpr int Dh   = 64;
constexpr int Mrows = Bsz * Sseq;   // 4096

// Scratch (device globals, allocation-free). All operands live as TWO bf16
// planes: hi = bf16(x), mid = bf16(x - hi). hi+mid recovers fp32 to ~2^-16.
__device__ __nv_bfloat16 g_Afh[(size_t)Mrows * Fdim];
__device__ __nv_bfloat16 g_Afm[(size_t)Mrows * Fdim];
__device__ __nv_bfloat16 g_Ath[(size_t)Mrows * Fdim];
__device__ __nv_bfloat16 g_Atm[(size_t)Mrows * Fdim];
__device__ __nv_bfloat16 g_Wqh[(size_t)Fdim * Fdim];      // w_q^T  [n][k]
__device__ __nv_bfloat16 g_Wqm[(size_t)Fdim * Fdim];
__device__ __nv_bfloat16 g_Wkvh[(size_t)2 * Fdim * Fdim]; // w_kv^T [n][k]
__device__ __nv_bfloat16 g_Wkvm[(size_t)2 * Fdim * Fdim];
__device__ __nv_bfloat16 g_Woh[(size_t)Fdim * Fdim];      // w_out^T [n][k]
__device__ __nv_bfloat16 g_Wom[(size_t)Fdim * Fdim];
__device__ __nv_bfloat16 g_Qh[(size_t)Mrows * Fdim];
__device__ __nv_bfloat16 g_Qm[(size_t)Mrows * Fdim];
__device__ __nv_bfloat16 g_Kh[(size_t)Mrows * Fdim];
__device__ __nv_bfloat16 g_Km[(size_t)Mrows * Fdim];
__device__ __nv_bfloat16 g_Vth[(size_t)Mrows * Fdim];     // V^T [b][h][d][s]
__device__ __nv_bfloat16 g_Vtm[(size_t)Mrows * Fdim];
__device__ __nv_bfloat16 g_Oh[(size_t)Mrows * Fdim];
__device__ __nv_bfloat16 g_Om[(size_t)Mrows * Fdim];

// ---------------------------------------------------------------------------
// PTX helpers
// ---------------------------------------------------------------------------
__device__ __forceinline__ void cp_async16(uint32_t saddr, const void* gptr) {
    asm volatile("cp.async.cg.shared.global [%0], [%1], 16;"
                 :: "r"(saddr), "l"(gptr));
}
__device__ __forceinline__ void cp_commit() {
    asm volatile("cp.async.commit_group;");
}
__device__ __forceinline__ void cp_wait0() {
    asm volatile("cp.async.wait_group 0;");
}

__device__ __forceinline__ void mma_bf16(
    float& d0, float& d1, float& d2, float& d3,
    uint32_t a0, uint32_t a1, uint32_t a2, uint32_t a3,
    uint32_t b0, uint32_t b1)
{
    asm volatile(
        "mma.sync.aligned.m16n8k16.row.col.f32.bf16.bf16.f32 "
        "{%0,%1,%2,%3},{%4,%5,%6,%7},{%8,%9},{%0,%1,%2,%3};"
        : "+f"(d0), "+f"(d1), "+f"(d2), "+f"(d3)
        : "r"(a0), "r"(a1), "r"(a2), "r"(a3), "r"(b0), "r"(b1));
}

__device__ __forceinline__ void bsplit(float v, __nv_bfloat16& h, __nv_bfloat16& m) {
    h = __float2bfloat16_rn(v);
    m = __float2bfloat16_rn(v - __bfloat162float(h));
}
__device__ __forceinline__ uint32_t bpack(__nv_bfloat16 lo, __nv_bfloat16 hi) {
    __nv_bfloat162 t;
    t.x = lo; t.y = hi;
    return *reinterpret_cast<uint32_t*>(&t);
}

// ---------------------------------------------------------------------------
// Pre-pass: elementwise split (no transpose) for activations [M][K].
// ---------------------------------------------------------------------------
__global__ __launch_bounds__(256) void asplit_kernel(
    const float* __restrict__ src, __nv_bfloat16* __restrict__ hi,
    __nv_bfloat16* __restrict__ mid, int n4)
{
    const int i = blockIdx.x * 256 + threadIdx.x;
    if (i >= n4) return;
    float4 v = ((const float4*)src)[i];
    __nv_bfloat16 h0, h1, h2, h3, m0, m1, m2, m3;
    bsplit(v.x, h0, m0); bsplit(v.y, h1, m1);
    bsplit(v.z, h2, m2); bsplit(v.w, h3, m3);
    ((uint2*)hi)[i]  = make_uint2(bpack(h0, h1), bpack(h2, h3));
    ((uint2*)mid)[i] = make_uint2(bpack(m0, m1), bpack(m2, m3));
}

// Pre-pass: split + transpose weights w[k][n] -> planes [n][k].
__global__ __launch_bounds__(256) void wsplit_kernel(
    const float* __restrict__ w, __nv_bfloat16* __restrict__ th,
    __nv_bfloat16* __restrict__ tm, int K, int N)
{
    __shared__ float ts[32][33];
    const int k0 = blockIdx.x * 32;
    const int n0 = blockIdx.y * 32;
    const int tx = threadIdx.x & 31;
    const int ty = threadIdx.x >> 5;
    #pragma unroll
    for (int i = 0; i < 4; i++)
        ts[ty + 8 * i][tx] = w[(size_t)(k0 + ty + 8 * i) * N + n0 + tx];
    __syncthreads();
    #pragma unroll
    for (int i = 0; i < 4; i++) {
        float v = ts[tx][ty + 8 * i];
        __nv_bfloat16 h, m;
        bsplit(v, h, m);
        const size_t o = (size_t)(n0 + ty + 8 * i) * K + k0 + tx;
        th[o] = h;
        tm[o] = m;
    }
}

// Row-0 fix: fully-masked row -> uniform softmax -> mean of V rows.
__global__ __launch_bounds__(256) void row0_kernel(
    const __nv_bfloat16* __restrict__ Vth, const __nv_bfloat16* __restrict__ Vtm,
    __nv_bfloat16* __restrict__ Oh, __nv_bfloat16* __restrict__ Om)
{
    __shared__ float red[256];
    const int f = blockIdx.x;
    const int b = blockIdx.y;
    const int h = f >> 6, d = f & 63;
    const size_t base = ((size_t)(b * 16 + h) * 64 + d) * 2048;
    float s = 0.f;
    for (int i = threadIdx.x; i < 2048; i += 256)
        s += __bfloat162float(Vth[base + i]) + __bfloat162float(Vtm[base + i]);
    red[threadIdx.x] = s;
    __syncthreads();
    for (int o = 128; o > 0; o >>= 1) {
        if (threadIdx.x < o) red[threadIdx.x] += red[threadIdx.x + o];
        __syncthreads();
    }
    if (threadIdx.x == 0) {
        const float v = red[0] * (1.f / 2048.f);
        __nv_bfloat16 hh, mm;
        bsplit(v, hh, mm);
        const size_t o = (size_t)(b * Sseq) * 1024 + f;
        Oh[o] = hh;
        Om[o] = mm;
    }
}

// ---------------------------------------------------------------------------
// bf16x3 GEMM core: C[M,N] = A[M,1024] @ W^T[n][k] (+bias via epilogue).
// CTA tile 128x256, BK=32, 256 threads, 8 warps of 64x64 warp tiles
// (2 m-slabs x 4 n-slabs) -> smem read redundancy A=4x->4x over 2x area,
// total crossbar traffic per flop cut ~35% vs 64x32 warp tiles.
// Hot loop: pure LDS + HMMA, B frags loaded in two nj-halves to bound regs.
// ---------------------------------------------------------------------------
constexpr int SW   = 20;                    // words per row (16 data + 4 pad)
constexpr int PLWA = 128 * SW;              // 2560 words per A plane
constexpr int PLWB = 256 * SW;              // 5120 words per B plane
constexpr int STAGE_W = 2 * PLWA + 2 * PLWB;        // 15360 words
constexpr int GEMM_SMEM = 2 * STAGE_W * 4;          // 122880 B

template <typename EPI>
__device__ __forceinline__ void gemm_mainloop(
    const __nv_bfloat16* __restrict__ Ah, const __nv_bfloat16* __restrict__ Am,
    const __nv_bfloat16* __restrict__ Bh, const __nv_bfloat16* __restrict__ Bm,
    int m0, int n0, uint32_t* smw, EPI epi)
{
    const uint32_t sbase = (uint32_t)__cvta_generic_to_shared(smw);
    const int tid  = threadIdx.x;
    const int warp = tid >> 5;
    const int lane = tid & 31;
    const int rbase = (warp & 1) * 64;        // 2 m-slabs of 64
    const int cbase = (warp >> 1) * 64;       // 4 n-slabs of 64
    const int lq  = lane >> 2;      // 0..7
    const int lc  = lane & 3;       // 0..3

    float acc[4][8][4];
    #pragma unroll
    for (int i = 0; i < 4; i++)
        #pragma unroll
        for (int j = 0; j < 8; j++)
            #pragma unroll
            for (int r = 0; r < 4; r++) acc[i][j][r] = 0.f;

    auto load_tile = [&](int kt, int st) {
        const int k0 = kt * 32;
        const uint32_t base = sbase + (uint32_t)(st * STAGE_W) * 4u;
        // A planes: 128 rows x 4 16B-chunks = 512 slots each
        #pragma unroll
        for (int it = 0; it < 2; it++) {
            const int slot = it * 256 + tid;
            const int row = slot >> 2, c4 = slot & 3;
            const uint32_t so = (uint32_t)(row * SW + c4 * 4) * 4u;
            const size_t ga = (size_t)(m0 + row) * 1024 + k0 + c4 * 8;
            cp_async16(base + so, &Ah[ga]);
            cp_async16(base + (uint32_t)(PLWA * 4) + so, &Am[ga]);
        }
        // B planes: 256 rows x 4 chunks = 1024 slots each
        #pragma unroll
        for (int it = 0; it < 4; it++) {
            const int slot = it * 256 + tid;
            const int row = slot >> 2, c4 = slot & 3;
            const uint32_t so = (uint32_t)(row * SW + c4 * 4) * 4u;
            const size_t gb = (size_t)(n0 + row) * 1024 + k0 + c4 * 8;
            cp_async16(base + (uint32_t)(2 * PLWA * 4) + so, &Bh[gb]);
            cp_async16(base + (uint32_t)((2 * PLWA + PLWB) * 4) + so, &Bm[gb]);
        }
    };

    load_tile(0, 0);
    cp_commit();

    for (int kt = 0; kt < 32; kt++) {
        cp_wait0();
        __syncthreads();   // orders compute(kt-1) before loads(kt+1) too
        if (kt + 1 < 32) { load_tile(kt + 1, (kt + 1) & 1); cp_commit(); }

        const uint32_t* AH = smw + (kt & 1) * STAGE_W;
        const uint32_t* AM = AH + PLWA;
        const uint32_t* BH = AH + 2 * PLWA;
        const uint32_t* BM = AH + 2 * PLWA + PLWB;

        #pragma unroll
        for (int ks = 0; ks < 2; ks++) {
            const int kk2 = ks * 8;
            uint32_t ah[4][4], am[4][4];
            #pragma unroll
            for (int mi = 0; mi < 4; mi++) {
                const int rr = rbase + mi * 16 + lq;
                const int o0 = rr * SW + kk2 + lc;
                const int o1 = (rr + 8) * SW + kk2 + lc;
                ah[mi][0] = AH[o0];     am[mi][0] = AM[o0];
                ah[mi][1] = AH[o1];     am[mi][1] = AM[o1];
                ah[mi][2] = AH[o0 + 4]; am[mi][2] = AM[o0 + 4];
                ah[mi][3] = AH[o1 + 4]; am[mi][3] = AM[o1 + 4];
            }
            #pragma unroll
            for (int njp = 0; njp < 2; njp++) {
                uint32_t bh[4][2], bm[4][2];
                #pragma unroll
                for (int j = 0; j < 4; j++) {
                    const int cc = cbase + (njp * 4 + j) * 8 + lq;
                    const int o = cc * SW + kk2 + lc;
                    bh[j][0] = BH[o];     bm[j][0] = BM[o];
                    bh[j][1] = BH[o + 4]; bm[j][1] = BM[o + 4];
                }
                #pragma unroll
                for (int mi = 0; mi < 4; mi++)
                    #pragma unroll
                    for (int j = 0; j < 4; j++) {
                        const int nj = njp * 4 + j;
                        mma_bf16(acc[mi][nj][0], acc[mi][nj][1],
                                 acc[mi][nj][2], acc[mi][nj][3],
                                 am[mi][0], am[mi][1], am[mi][2], am[mi][3],
                                 bh[j][0], bh[j][1]);
                        mma_bf16(acc[mi][nj][0], acc[mi][nj][1],
                                 acc[mi][nj][2], acc[mi][nj][3],
                                 ah[mi][0], ah[mi][1], ah[mi][2], ah[mi][3],
                                 bm[j][0], bm[j][1]);
                        mma_bf16(acc[mi][nj][0], acc[mi][nj][1],
                                 acc[mi][nj][2], acc[mi][nj][3],
                                 ah[mi][0], ah[mi][1], ah[mi][2], ah[mi][3],
                                 bh[j][0], bh[j][1]);
                    }
            }
        }
    }
    __syncthreads();
    epi(acc, rbase, cbase, lq, lc);
}

// Merged Q + KV projection. grid.x = 384 (Q: 128 CTAs, KV: 256 CTAs).
__global__ __launch_bounds__(256, 1) void qkv_gemm_kernel(
    const __nv_bfloat16* __restrict__ Afh, const __nv_bfloat16* __restrict__ Afm,
    const __nv_bfloat16* __restrict__ Ath, const __nv_bfloat16* __restrict__ Atm,
    const __nv_bfloat16* __restrict__ Wqh, const __nv_bfloat16* __restrict__ Wqm,
    const __nv_bfloat16* __restrict__ Wkvh, const __nv_bfloat16* __restrict__ Wkvm,
    const float* __restrict__ bq, const float* __restrict__ bkv,
    __nv_bfloat16* __restrict__ Qh, __nv_bfloat16* __restrict__ Qm,
    __nv_bfloat16* __restrict__ Kh, __nv_bfloat16* __restrict__ Km,
    __nv_bfloat16* __restrict__ Vth, __nv_bfloat16* __restrict__ Vtm)
{
    extern __shared__ uint32_t smw[];
    const int bx = blockIdx.x;

    const __nv_bfloat16 *Ah, *Am, *Bh, *Bm;
    const float* bias;
    int m0, n0, is_v = 0, ncol;
    if (bx < 128) {
        Ah = Afh; Am = Afm; Bh = Wqh; Bm = Wqm; bias = bq;
        m0 = (bx >> 2) * 128; n0 = (bx & 3) * 256; ncol = n0;
    } else {
        const int bxx = bx - 128;
        Ah = Ath; Am = Atm; Bh = Wkvh; Bm = Wkvm; bias = bkv;
        m0 = (bxx >> 3) * 128; n0 = (bxx & 7) * 256;
        if (n0 < 1024) { ncol = n0; }
        else           { ncol = n0 - 1024; is_v = 1; }
    }

    gemm_mainloop(Ah, Am, Bh, Bm, m0, n0, smw,
        [&](float (&acc)[4][8][4], int rbase, int cbase, int lq, int lc) {
            #pragma unroll
            for (int mi = 0; mi < 4; mi++) {
                const int r0 = m0 + rbase + mi * 16 + lq;
                #pragma unroll
                for (int nj = 0; nj < 8; nj++) {
                    const int col = ncol + cbase + nj * 8 + lc * 2;
                    const float b0 = bias[n0 - ncol + col];
                    const float b1 = bias[n0 - ncol + col + 1];
                    float v00 = acc[mi][nj][0] + b0;
                    float v01 = acc[mi][nj][1] + b1;
                    float v10 = acc[mi][nj][2] + b0;
                    float v11 = acc[mi][nj][3] + b1;
                    __nv_bfloat16 h00, h01, h10, h11, q00, q01, q10, q11;
                    bsplit(v00, h00, q00); bsplit(v01, h01, q01);
                    bsplit(v10, h10, q10); bsplit(v11, h11, q11);
                    if (!is_v) {
                        __nv_bfloat16* Dh = (bx < 128) ? Qh : Kh;
                        __nv_bfloat16* Dm = (bx < 128) ? Qm : Km;
                        const size_t o0 = (size_t)r0 * 1024 + col;
                        const size_t o1 = (size_t)(r0 + 8) * 1024 + col;
                        *(uint32_t*)&Dh[o0] = bpack(h00, h01);
                        *(uint32_t*)&Dh[o1] = bpack(h10, h11);
                        *(uint32_t*)&Dm[o0] = bpack(q00, q01);
                        *(uint32_t*)&Dm[o1] = bpack(q10, q11);
                    } else {
                        // V transposed: [b][h][d][s]
                        const int h = col >> 6, d = col & 63;
                        const int bl0 = r0 >> 11, s0 = r0 & 2047;
                        const int bl1 = (r0 + 8) >> 11, s1 = (r0 + 8) & 2047;
                        const size_t i00 = ((size_t)(bl0 * 16 + h) * 64 + d) * 2048 + s0;
                        const size_t i10 = ((size_t)(bl1 * 16 + h) * 64 + d) * 2048 + s1;
                        Vth[i00] = h00;          Vtm[i00] = q00;
                        Vth[i00 + 2048] = h01;   Vtm[i00 + 2048] = q01;
                        Vth[i10] = h10;          Vtm[i10] = q10;
                        Vth[i10 + 2048] = h11;   Vtm[i10 + 2048] = q11;
                    }
                }
            }
        });
}

// Output projection: out = O @ w_out + b_out (fp32 store).
__global__ __launch_bounds__(256, 1) void out_gemm_kernel(
    const __nv_bfloat16* __restrict__ Ah, const __nv_bfloat16* __restrict__ Am,
    const __nv_bfloat16* __restrict__ Bh, const __nv_bfloat16* __restrict__ Bm,
    const float* __restrict__ bias, float* __restrict__ C)
{
    extern __shared__ uint32_t smw[];
    const int m0 = blockIdx.y * 128;
    const int n0 = blockIdx.x * 256;
    gemm_mainloop(Ah, Am, Bh, Bm, m0, n0, smw,
        [&](float (&acc)[4][8][4], int rbase, int cbase, int lq, int lc) {
            #pragma unroll
            for (int mi = 0; mi < 4; mi++) {
                const int r0 = m0 + rbase + mi * 16 + lq;
                #pragma unroll
                for (int nj = 0; nj < 8; nj++) {
                    const int col = n0 + cbase + nj * 8 + lc * 2;
                    const float b0 = bias[col], b1 = bias[col + 1];
                    *(float2*)&C[(size_t)r0 * Fdim + col] =
                        make_float2(acc[mi][nj][0] + b0, acc[mi][nj][1] + b1);
                    *(float2*)&C[(size_t)(r0 + 8) * Fdim + col] =
                        make_float2(acc[mi][nj][2] + b0, acc[mi][nj][3] + b1);
                }
            }
        });
}

// ---------------------------------------------------------------------------
// bf16x3 flash attention (unchanged from the 590us best).
// ---------------------------------------------------------------------------
constexpr int FST = 36;
constexpr int FTW = 64 * FST;
constexpr int FLASH_SMEM = 8 * FTW * 4;

__global__ __launch_bounds__(256) void flash_mma_kernel(
    const __nv_bfloat16* __restrict__ Qh, const __nv_bfloat16* __restrict__ Qm,
    const __nv_bfloat16* __restrict__ Kh, const __nv_bfloat16* __restrict__ Km,
    const __nv_bfloat16* __restrict__ Vth, const __nv_bfloat16* __restrict__ Vtm,
    __nv_bfloat16* __restrict__ Oh, __nv_bfloat16* __restrict__ Om)
{
    extern __shared__ uint32_t smw[];
    const uint32_t sbase = (uint32_t)__cvta_generic_to_shared(smw);

    const int t = 15 - (int)blockIdx.x;
    const int h = blockIdx.y;
    const int b = blockIdx.z;
    const int tid  = threadIdx.x;
    const int warp = tid >> 5;
    const int lane = tid & 31;
    const int lq  = lane >> 2;
    const int lc  = lane & 3;

    auto plane = [&](int p, int st) { return (uint32_t)((p * 2 + st) * FTW); };

    auto load_kv = [&](int kc, int st) {
        #pragma unroll
        for (int it = 0; it < 2; it++) {
            const int slot = it * 256 + tid;
            const int row = slot >> 3;
            const int c8 = slot & 7;
            const uint32_t so = (uint32_t)(row * FST + c8 * 4) * 4u;
            const size_t gk = (size_t)(b * Sseq + kc * 64 + row) * 1024 + h * 64 + c8 * 8;
            cp_async16(sbase + (plane(0, st)) * 4u + so, &Kh[gk]);
            cp_async16(sbase + (plane(1, st)) * 4u + so, &Km[gk]);
            const size_t gv = ((size_t)(b * 16 + h) * 64 + row) * 2048 + kc * 64 + c8 * 8;
            cp_async16(sbase + (plane(2, st)) * 4u + so, &Vth[gv]);
            cp_async16(sbase + (plane(3, st)) * 4u + so, &Vtm[gv]);
        }
    };

    load_kv(0, 0);
    cp_commit();

    const uint32_t* Qh32 = (const uint32_t*)Qh;
    const uint32_t* Qm32 = (const uint32_t*)Qm;
    uint32_t qh[4][4], qm[4][4];
    {
        const int qrow = b * Sseq + t * 128 + warp * 16 + lq;
        const size_t qb0 = (size_t)qrow * 512 + h * 32;
        const size_t qb1 = qb0 + 8 * 512;
        #pragma unroll
        for (int ks = 0; ks < 4; ks++) {
            const int o = ks * 8 + lc;
            qh[ks][0] = Qh32[qb0 + o];     qm[ks][0] = Qm32[qb0 + o];
            qh[ks][1] = Qh32[qb1 + o];     qm[ks][1] = Qm32[qb1 + o];
            qh[ks][2] = Qh32[qb0 + o + 4]; qm[ks][2] = Qm32[qb0 + o + 4];
            qh[ks][3] = Qh32[qb1 + o + 4]; qm[ks][3] = Qm32[qb1 + o + 4];
        }
    }

    float oacc[8][4];
    #pragma unroll
    for (int nt = 0; nt < 8; nt++)
        #pragma unroll
        for (int r = 0; r < 4; r++) oacc[nt][r] = 0.f;
    float m0 = -3.0e38f, m1 = -3.0e38f, l0 = 0.f, l1 = 0.f;

    const int row0 = t * 128 + warp * 16 + lq;
    const int row1 = row0 + 8;
    const int nkc = 2 * t + 2;

    for (int kc = 0; kc < nkc; kc++) {
        cp_wait0();
        __syncthreads();
        if (kc + 1 < nkc) { load_kv(kc + 1, (kc + 1) & 1); cp_commit(); }

        const int st = kc & 1;
        const uint32_t* KH = smw + plane(0, st);
        const uint32_t* KM = smw + plane(1, st);
        const uint32_t* VH = smw + plane(2, st);
        const uint32_t* VM = smw + plane(3, st);

        float sacc[8][4];
        #pragma unroll
        for (int nt = 0; nt < 8; nt++)
            #pragma unroll
            for (int r = 0; r < 4; r++) sacc[nt][r] = 0.f;

        #pragma unroll
        for (int ks = 0; ks < 4; ks++) {
            #pragma unroll
            for (int nt = 0; nt < 8; nt++) {
                const int ko = (nt * 8 + lq) * FST + ks * 8 + lc;
                const uint32_t bh0 = KH[ko], bh1 = KH[ko + 4];
                const uint32_t bm0 = KM[ko], bm1 = KM[ko + 4];
                mma_bf16(sacc[nt][0], sacc[nt][1], sacc[nt][2], sacc[nt][3],
                         qm[ks][0], qm[ks][1], qm[ks][2], qm[ks][3], bh0, bh1);
                mma_bf16(sacc[nt][0], sacc[nt][1], sacc[nt][2], sacc[nt][3],
                         qh[ks][0], qh[ks][1], qh[ks][2], qh[ks][3], bm0, bm1);
                mma_bf16(sacc[nt][0], sacc[nt][1], sacc[nt][2], sacc[nt][3],
                         qh[ks][0], qh[ks][1], qh[ks][2], qh[ks][3], bh0, bh1);
            }
        }

        #pragma unroll
        for (int nt = 0; nt < 8; nt++) {
            const int cb = kc * 64 + nt * 8 + 2 * lc;
            if (cb     >= row0) sacc[nt][0] = -1.0e12f;
            if (cb + 1 >= row0) sacc[nt][1] = -1.0e12f;
            if (cb     >= row1) sacc[nt][2] = -1.0e12f;
            if (cb + 1 >= row1) sacc[nt][3] = -1.0e12f;
        }

        float mt0 = -3.0e38f, mt1 = -3.0e38f;
        #pragma unroll
        for (int nt = 0; nt < 8; nt++) {
            mt0 = fmaxf(mt0, fmaxf(sacc[nt][0], sacc[nt][1]));
            mt1 = fmaxf(mt1, fmaxf(sacc[nt][2], sacc[nt][3]));
        }
        mt0 = fmaxf(mt0, __shfl_xor_sync(0xffffffffu, mt0, 1));
        mt0 = fmaxf(mt0, __shfl_xor_sync(0xffffffffu, mt0, 2));
        mt1 = fmaxf(mt1, __shfl_xor_sync(0xffffffffu, mt1, 1));
        mt1 = fmaxf(mt1, __shfl_xor_sync(0xffffffffu, mt1, 2));
        const float mn0 = fmaxf(m0, mt0);
        const float mn1 = fmaxf(m1, mt1);
        const float sc0 = __expf(m0 - mn0);
        const float sc1 = __expf(m1 - mn1);
        float ls0 = 0.f, ls1 = 0.f;
        #pragma unroll
        for (int nt = 0; nt < 8; nt++) {
            sacc[nt][0] = __expf(sacc[nt][0] - mn0);
            sacc[nt][1] = __expf(sacc[nt][1] - mn0);
            sacc[nt][2] = __expf(sacc[nt][2] - mn1);
            sacc[nt][3] = __expf(sacc[nt][3] - mn1);
            ls0 += sacc[nt][0] + sacc[nt][1];
            ls1 += sacc[nt][2] + sacc[nt][3];
        }
        l0 = l0 * sc0 + ls0;
        l1 = l1 * sc1 + ls1;
        m0 = mn0; m1 = mn1;
        #pragma unroll
        for (int nt = 0; nt < 8; nt++) {
            oacc[nt][0] *= sc0; oacc[nt][1] *= sc0;
            oacc[nt][2] *= sc1; oacc[nt][3] *= sc1;
        }

        #pragma unroll
        for (int ks = 0; ks < 4; ks++) {
            __nv_bfloat16 h0, h1, h2, h3, h4, h5, h6, h7;
            __nv_bfloat16 w0, w1, w2, w3, w4, w5, w6, w7;
            bsplit(sacc[2 * ks][0], h0, w0); bsplit(sacc[2 * ks][1], h1, w1);
            bsplit(sacc[2 * ks][2], h2, w2); bsplit(sacc[2 * ks][3], h3, w3);
            bsplit(sacc[2 * ks + 1][0], h4, w4); bsplit(sacc[2 * ks + 1][1], h5, w5);
            bsplit(sacc[2 * ks + 1][2], h6, w6); bsplit(sacc[2 * ks + 1][3], h7, w7);
            const uint32_t pah0 = bpack(h0, h1), pah1 = bpack(h2, h3);
            const uint32_t pah2 = bpack(h4, h5), pah3 = bpack(h6, h7);
            const uint32_t pam0 = bpack(w0, w1), pam1 = bpack(w2, w3);
            const uint32_t pam2 = bpack(w4, w5), pam3 = bpack(w6, w7);
            #pragma unroll
            for (int nt = 0; nt < 8; nt++) {
                const int vo = (nt * 8 + lq) * FST + ks * 8 + lc;
                const uint32_t vh0 = VH[vo], vh1 = VH[vo + 4];
                const uint32_t vm0 = VM[vo], vm1 = VM[vo + 4];
                mma_bf16(oacc[nt][0], oacc[nt][1], oacc[nt][2], oacc[nt][3],
                         pam0, pam1, pam2, pam3, vh0, vh1);
                mma_bf16(oacc[nt][0], oacc[nt][1], oacc[nt][2], oacc[nt][3],
                         pah0, pah1, pah2, pah3, vm0, vm1);
                mma_bf16(oacc[nt][0], oacc[nt][1], oacc[nt][2], oacc[nt][3],
                         pah0, pah1, pah2, pah3, vh0, vh1);
            }
        }
    }

    l0 += __shfl_xor_sync(0xffffffffu, l0, 1);
    l0 += __shfl_xor_sync(0xffffffffu, l0, 2);
    l1 += __shfl_xor_sync(0xffffffffu, l1, 1);
    l1 += __shfl_xor_sync(0xffffffffu, l1, 2);
    const float inv0 = 1.f / l0;
    const float inv1 = 1.f / l1;

    const size_t ob = ((size_t)(b * Sseq + t * 128 + warp * 16 + lq)) * 1024 + h * 64;
    #pragma unroll
    for (int nt = 0; nt < 8; nt++) {
        const int cb = nt * 8 + 2 * lc;
        float v00 = oacc[nt][0] * inv0, v01 = oacc[nt][1] * inv0;
        float v10 = oacc[nt][2] * inv1, v11 = oacc[nt][3] * inv1;
        __nv_bfloat16 h00, h01, h10, h11, m00, m01, m10, m11;
        bsplit(v00, h00, m00); bsplit(v01, h01, m01);
        bsplit(v10, h10, m10); bsplit(v11, h11, m11);
        *(uint32_t*)&Oh[ob + cb] = bpack(h00, h01);
        *(uint32_t*)&Oh[ob + 8 * 1024 + cb] = bpack(h10, h11);
        *(uint32_t*)&Om[ob + cb] = bpack(m00, m01);
        *(uint32_t*)&Om[ob + 8 * 1024 + cb] = bpack(m10, m11);
    }
}

// ---------------------------------------------------------------------------
extern "C" void kernel_launch(void* const* d_in, const int* in_sizes, int n_in,
                              void* d_out, int out_size)
{
    (void)in_sizes; (void)n_in; (void)out_size;
    const float* attend_from = (const float*)d_in[0];
    const float* attend_to   = (const float*)d_in[1];
    const float* w_q   = (const float*)d_in[2];
    const float* b_q   = (const float*)d_in[3];
    const float* w_kv  = (const float*)d_in[4];
    const float* b_kv  = (const float*)d_in[5];
    const float* w_out = (const float*)d_in[6];
    const float* b_out = (const float*)d_in[7];
    float* out = (float*)d_out;

    __nv_bfloat16 *afh, *afm, *ath, *atm, *wqh, *wqm, *wkvh, *wkvm, *woh, *wom;
    __nv_bfloat16 *qh, *qm, *kh, *km, *vth, *vtm, *oh, *om;
    cudaGetSymbolAddress((void**)&afh, g_Afh);
    cudaGetSymbolAddress((void**)&afm, g_Afm);
    cudaGetSymbolAddress((void**)&ath, g_Ath);
    cudaGetSymbolAddress((void**)&atm, g_Atm);
    cudaGetSymbolAddress((void**)&wqh, g_Wqh);
    cudaGetSymbolAddress((void**)&wqm, g_Wqm);
    cudaGetSymbolAddress((void**)&wkvh, g_Wkvh);
    cudaGetSymbolAddress((void**)&wkvm, g_Wkvm);
    cudaGetSymbolAddress((void**)&woh, g_Woh);
    cudaGetSymbolAddress((void**)&wom, g_Wom);
    cudaGetSymbolAddress((void**)&qh, g_Qh);
    cudaGetSymbolAddress((void**)&qm, g_Qm);
    cudaGetSymbolAddress((void**)&kh, g_Kh);
    cudaGetSymbolAddress((void**)&km, g_Km);
    cudaGetSymbolAddress((void**)&vth, g_Vth);
    cudaGetSymbolAddress((void**)&vtm, g_Vtm);
    cudaGetSymbolAddress((void**)&oh, g_Oh);
    cudaGetSymbolAddress((void**)&om, g_Om);

    cudaFuncSetAttribute(qkv_gemm_kernel,
                         cudaFuncAttributeMaxDynamicSharedMemorySize, GEMM_SMEM);
    cudaFuncSetAttribute(out_gemm_kernel,
                         cudaFuncAttributeMaxDynamicSharedMemorySize, GEMM_SMEM);
    cudaFuncSetAttribute(flash_mma_kernel,
                         cudaFuncAttributeMaxDynamicSharedMemorySize, FLASH_SMEM);

    // 0) pre-split activations, split+transpose weights
    {
        const int nA = Mrows * Fdim / 4;
        asplit_kernel<<<(nA + 255) / 256, 256>>>(attend_from, afh, afm, nA);
        asplit_kernel<<<(nA + 255) / 256, 256>>>(attend_to,   ath, atm, nA);
        wsplit_kernel<<<dim3(32, 32), 256>>>(w_q,   wqh,  wqm,  1024, 1024);
        wsplit_kernel<<<dim3(32, 64), 256>>>(w_kv,  wkvh, wkvm, 1024, 2048);
        wsplit_kernel<<<dim3(32, 32), 256>>>(w_out, woh,  wom,  1024, 1024);
    }

    // 1) merged Q + KV projection (128 Q CTAs + 256 KV CTAs)
    qkv_gemm_kernel<<<384, 256, GEMM_SMEM>>>(
        afh, afm, ath, atm, wqh, wqm, wkvh, wkvm, b_q, b_kv,
        qh, qm, kh, km, vth, vtm);

    // 2) flash attention (row s=0 via row0_kernel)
    {
        dim3 grid(Sseq / 128, Hh, Bsz);
        flash_mma_kernel<<<grid, 256, FLASH_SMEM>>>(
            qh, qm, kh, km, vth, vtm, oh, om);
    }

    // 2b) exact fix-up for fully-masked row s=0
    {
        dim3 grid(1024, Bsz);
        row0_kernel<<<grid, 256>>>(vth, vtm, oh, om);
    }

    // 3) output projection
    {
        dim3 grid(Fdim / 256, Mrows / 128);
        out_gemm_kernel<<<grid, 256, GEMM_SMEM>>>(oh, om, woh, wom, b_out, out);
    }
}